// round 10
// baseline (speedup 1.0000x reference)
#include <cuda_runtime.h>
#include <stdint.h>

#define N_NODES  50000
#define N_EDGES  800000
#define IN_F     128
#define OUT_F    128

#define SCAN_T   256
#define SCAN_B   ((N_NODES + SCAN_T - 1) / SCAN_T)   // 196

#define NUM_SM   148
#define TILE_M   128
#define N_TILES  ((N_NODES + TILE_M - 1) / TILE_M)   // 391

// -------------------- device scratch (no allocation allowed) ---------------
__device__ __align__(16) float g_agg[N_NODES * IN_F];  // normalized h rows
__device__ int   g_cnt4[4 * N_NODES];   // replicated histograms (stripe = edge%4)
__device__ int   g_base4[4 * N_NODES];  // per-(node,replica) output bases; row0 = CSR start
__device__ int   g_cnt[N_NODES];        // per-node totals
__device__ __align__(16) int g_rank[N_EDGES];  // rank within (node,replica)
__device__ int   g_srcs[N_EDGES];       // edge sources grouped by dst
__device__ int   g_bsums[SCAN_B];

// -------------------- 1) histogram (replicated) + rank capture -------------
__global__ void hist_kernel(const int* __restrict__ ei) {
    const int e4 = blockIdx.x * blockDim.x + threadIdx.x;
    if (e4 >= N_EDGES / 4) return;
    int4 d = reinterpret_cast<const int4*>(ei + N_EDGES)[e4];
    d.x = min(max(d.x, 0), N_NODES - 1);
    d.y = min(max(d.y, 0), N_NODES - 1);
    d.z = min(max(d.z, 0), N_NODES - 1);
    d.w = min(max(d.w, 0), N_NODES - 1);
    int4 r;
    r.x = atomicAdd(&g_cnt4[0 * N_NODES + d.x], 1);
    r.y = atomicAdd(&g_cnt4[1 * N_NODES + d.y], 1);
    r.z = atomicAdd(&g_cnt4[2 * N_NODES + d.z], 1);
    r.w = atomicAdd(&g_cnt4[3 * N_NODES + d.w], 1);
    reinterpret_cast<int4*>(g_rank)[e4] = r;
}

// -------------------- 2) scanA: totals + per-block sums --------------------
__global__ void scanA_kernel() {
    __shared__ int s[SCAN_T];
    const int gid = blockIdx.x * SCAN_T + threadIdx.x;
    int tot = 0;
    if (gid < N_NODES) {
        tot = g_cnt4[gid] + g_cnt4[N_NODES + gid]
            + g_cnt4[2 * N_NODES + gid] + g_cnt4[3 * N_NODES + gid];
        g_cnt[gid] = tot;
    }
    s[threadIdx.x] = tot;
    __syncthreads();
    #pragma unroll
    for (int o = SCAN_T / 2; o > 0; o >>= 1) {
        if (threadIdx.x < o) s[threadIdx.x] += s[threadIdx.x + o];
        __syncthreads();
    }
    if (threadIdx.x == 0) g_bsums[blockIdx.x] = s[0];
}

// -------------------- 3) scanB: exclusive scan + replica bases -------------
__global__ void scanB_kernel() {
    __shared__ int sb[SCAN_T];
    __shared__ int st[SCAN_T];
    const int tid = threadIdx.x;

    int bv = (tid < SCAN_B) ? g_bsums[tid] : 0;
    sb[tid] = bv;
    __syncthreads();
    #pragma unroll
    for (int o = 1; o < SCAN_T; o <<= 1) {
        int t = (tid >= o) ? sb[tid - o] : 0;
        __syncthreads();
        sb[tid] += t;
        __syncthreads();
    }
    const int base = (blockIdx.x > 0) ? sb[blockIdx.x - 1] : 0;

    const int gid = blockIdx.x * SCAN_T + tid;
    int c = (gid < N_NODES) ? g_cnt[gid] : 0;
    st[tid] = c;
    __syncthreads();
    #pragma unroll
    for (int o = 1; o < SCAN_T; o <<= 1) {
        int t = (tid >= o) ? st[tid - o] : 0;
        __syncthreads();
        st[tid] += t;
        __syncthreads();
    }
    if (gid < N_NODES) {
        const int excl = base + st[tid] - c;
        const int c0 = g_cnt4[gid];
        const int c1 = g_cnt4[N_NODES + gid];
        const int c2 = g_cnt4[2 * N_NODES + gid];
        g_base4[gid]               = excl;          // row0 base == CSR row start
        g_base4[N_NODES + gid]     = excl + c0;
        g_base4[2 * N_NODES + gid] = excl + c0 + c1;
        g_base4[3 * N_NODES + gid] = excl + c0 + c1 + c2;
    }
}

// -------------------- 4) bucket-fill: NO atomics (base + rank) -------------
__global__ void fill_kernel(const int* __restrict__ ei) {
    const int e4 = blockIdx.x * blockDim.x + threadIdx.x;
    if (e4 >= N_EDGES / 4) return;
    int4 s = reinterpret_cast<const int4*>(ei)[e4];
    int4 d = reinterpret_cast<const int4*>(ei + N_EDGES)[e4];
    int4 r = reinterpret_cast<const int4*>(g_rank)[e4];
    s.x = min(max(s.x, 0), N_NODES - 1);
    s.y = min(max(s.y, 0), N_NODES - 1);
    s.z = min(max(s.z, 0), N_NODES - 1);
    s.w = min(max(s.w, 0), N_NODES - 1);
    d.x = min(max(d.x, 0), N_NODES - 1);
    d.y = min(max(d.y, 0), N_NODES - 1);
    d.z = min(max(d.z, 0), N_NODES - 1);
    d.w = min(max(d.w, 0), N_NODES - 1);
    const int p0 = g_base4[0 * N_NODES + d.x] + r.x;
    const int p1 = g_base4[1 * N_NODES + d.y] + r.y;
    const int p2 = g_base4[2 * N_NODES + d.z] + r.z;
    const int p3 = g_base4[3 * N_NODES + d.w] + r.w;
    g_srcs[p0] = s.x;
    g_srcs[p1] = s.y;
    g_srcs[p2] = s.z;
    g_srcs[p3] = s.w;
}

// -------------------- 5) gather-aggregate: TWO nodes per warp --------------
// Each warp interleaves rounds of 4 gathers for node A and node B:
// 8 independent loads + 2 independent acc chains in flight per iteration.
// Loop conditions are warp-uniform (derived from per-node counts).
__global__ void __launch_bounds__(256)
agg_kernel(const float4* __restrict__ x4) {
    const int wg = (blockIdx.x * blockDim.x + threadIdx.x) >> 5;
    const int lane = threadIdx.x & 31;
    const int nodeA = wg * 2;
    if (nodeA >= N_NODES) return;
    const int nodeB = nodeA + 1;
    const bool hasB = (nodeB < N_NODES);

    int eA = g_base4[nodeA];
    const int cntA = g_cnt[nodeA];
    int endA = eA + cntA;

    int eB = 0, endB = 0, cntB = 0;
    if (hasB) {
        eB = g_base4[nodeB];
        cntB = g_cnt[nodeB];
        endB = eB + cntB;
    }

    float4 aA0 = make_float4(0.f, 0.f, 0.f, 0.f);
    float4 aA1 = make_float4(0.f, 0.f, 0.f, 0.f);
    float4 aB0 = make_float4(0.f, 0.f, 0.f, 0.f);
    float4 aB1 = make_float4(0.f, 0.f, 0.f, 0.f);

    while ((endA - eA >= 4) || (endB - eB >= 4)) {
        const bool doA = (endA - eA) >= 4;
        const bool doB = (endB - eB) >= 4;

        int ia0, ia1, ia2, ia3, ib0, ib1, ib2, ib3;
        if (doA) {
            ia0 = g_srcs[eA];     ia1 = g_srcs[eA + 1];
            ia2 = g_srcs[eA + 2]; ia3 = g_srcs[eA + 3];
        }
        if (doB) {
            ib0 = g_srcs[eB];     ib1 = g_srcs[eB + 1];
            ib2 = g_srcs[eB + 2]; ib3 = g_srcs[eB + 3];
        }

        float4 vA0, vA1, vA2, vA3, vB0, vB1, vB2, vB3;
        if (doA) {
            vA0 = __ldg(&x4[ia0 * 32 + lane]);
            vA1 = __ldg(&x4[ia1 * 32 + lane]);
            vA2 = __ldg(&x4[ia2 * 32 + lane]);
            vA3 = __ldg(&x4[ia3 * 32 + lane]);
        }
        if (doB) {
            vB0 = __ldg(&x4[ib0 * 32 + lane]);
            vB1 = __ldg(&x4[ib1 * 32 + lane]);
            vB2 = __ldg(&x4[ib2 * 32 + lane]);
            vB3 = __ldg(&x4[ib3 * 32 + lane]);
        }

        if (doA) {
            aA0.x += vA0.x; aA0.y += vA0.y; aA0.z += vA0.z; aA0.w += vA0.w;
            aA1.x += vA1.x; aA1.y += vA1.y; aA1.z += vA1.z; aA1.w += vA1.w;
            aA0.x += vA2.x; aA0.y += vA2.y; aA0.z += vA2.z; aA0.w += vA2.w;
            aA1.x += vA3.x; aA1.y += vA3.y; aA1.z += vA3.z; aA1.w += vA3.w;
            eA += 4;
        }
        if (doB) {
            aB0.x += vB0.x; aB0.y += vB0.y; aB0.z += vB0.z; aB0.w += vB0.w;
            aB1.x += vB1.x; aB1.y += vB1.y; aB1.z += vB1.z; aB1.w += vB1.w;
            aB0.x += vB2.x; aB0.y += vB2.y; aB0.z += vB2.z; aB0.w += vB2.w;
            aB1.x += vB3.x; aB1.y += vB3.y; aB1.z += vB3.z; aB1.w += vB3.w;
            eB += 4;
        }
    }

    // tails (<=3 each), all loads issued before any consumption
    {
        const int remA = endA - eA;          // 0..3
        const int remB = endB - eB;          // 0..3
        int ia[3], ib[3];
        #pragma unroll
        for (int i = 0; i < 3; i++) {
            ia[i] = (i < remA) ? g_srcs[eA + i] : 0;
            ib[i] = (i < remB) ? g_srcs[eB + i] : 0;
        }
        float4 va[3], vb[3];
        #pragma unroll
        for (int i = 0; i < 3; i++) {
            if (i < remA) va[i] = __ldg(&x4[ia[i] * 32 + lane]);
            if (i < remB) vb[i] = __ldg(&x4[ib[i] * 32 + lane]);
        }
        #pragma unroll
        for (int i = 0; i < 3; i++) {
            if (i < remA) {
                float4* a = (i & 1) ? &aA1 : &aA0;
                a->x += va[i].x; a->y += va[i].y; a->z += va[i].z; a->w += va[i].w;
            }
            if (i < remB) {
                float4* a = (i & 1) ? &aB1 : &aB0;
                a->x += vb[i].x; a->y += vb[i].y; a->z += vb[i].z; a->w += vb[i].w;
            }
        }
    }

    {
        const float inv = 1.0f / fmaxf((float)cntA, 1.0f);
        float4 r;
        r.x = (aA0.x + aA1.x) * inv;
        r.y = (aA0.y + aA1.y) * inv;
        r.z = (aA0.z + aA1.z) * inv;
        r.w = (aA0.w + aA1.w) * inv;
        reinterpret_cast<float4*>(g_agg)[(size_t)nodeA * 32 + lane] = r;
    }
    if (hasB) {
        const float inv = 1.0f / fmaxf((float)cntB, 1.0f);
        float4 r;
        r.x = (aB0.x + aB1.x) * inv;
        r.y = (aB0.y + aB1.y) * inv;
        r.z = (aB0.z + aB1.z) * inv;
        r.w = (aB0.w + aB1.w) * inv;
        reinterpret_cast<float4*>(g_agg)[(size_t)nodeB * 32 + lane] = r;
    }
}

// -------------------- 6) persistent double-buffered GEMM -------------------
__device__ __forceinline__ void issue_h_tile(int tile, float* buf, int tid) {
    const int m0 = tile * TILE_M;
    const float4* aggbase = reinterpret_cast<const float4*>(g_agg);
    #pragma unroll
    for (int j = 0; j < 16; j++) {
        const int i = tid + j * 256;
        const int r = i >> 5;
        const int c = i & 31;
        const int m = min(m0 + r, N_NODES - 1);
        const float4* src = aggbase + (size_t)m * 32 + c;
        unsigned saddr = (unsigned)__cvta_generic_to_shared(buf + i * 4);
        asm volatile("cp.async.cg.shared.global [%0], [%1], 16;"
                     :: "r"(saddr), "l"(src));
    }
    asm volatile("cp.async.commit_group;");
}

__global__ void __launch_bounds__(256, 1)
gemm_kernel(float* __restrict__ out, const float* __restrict__ W,
            const float* __restrict__ b) {
    extern __shared__ float sm[];
    float* Wsm   = sm;
    float* Hbuf0 = sm + IN_F * OUT_F;
    float* Hbuf1 = Hbuf0 + TILE_M * IN_F;

    const int tid = threadIdx.x;

    int tile0 = blockIdx.x;
    if (tile0 < N_TILES) issue_h_tile(tile0, Hbuf0, tid);

    #pragma unroll 4
    for (int i = tid; i < OUT_F * IN_F; i += 256) {
        const int n = i >> 7;
        const int k = i & 127;
        Wsm[k * OUT_F + n] = W[i];
    }

    const int rowg = tid >> 4;
    const int colg = tid & 15;
    const int r0   = rowg * 8;
    const int n0   = colg * 8;

    float bb[8];
    #pragma unroll
    for (int j = 0; j < 8; j++) bb[j] = b[n0 + j];

    int it = 0;
    for (int tile = blockIdx.x; tile < N_TILES; tile += NUM_SM, it++) {
        float* cur = (it & 1) ? Hbuf1 : Hbuf0;
        float* nxt = (it & 1) ? Hbuf0 : Hbuf1;
        const int ntile = tile + NUM_SM;
        if (ntile < N_TILES) {
            issue_h_tile(ntile, nxt, tid);
            asm volatile("cp.async.wait_group 1;");
        } else {
            asm volatile("cp.async.wait_group 0;");
        }
        __syncthreads();

        const float4* Hsm4 = reinterpret_cast<const float4*>(cur);

        unsigned long long acc[8][4];
        #pragma unroll
        for (int i = 0; i < 8; i++)
            #pragma unroll
            for (int j = 0; j < 4; j++) acc[i][j] = 0ULL;

        for (int kk = 0; kk < IN_F; kk += 4) {
            float4 h4[8];
            #pragma unroll
            for (int i = 0; i < 8; i++)
                h4[i] = Hsm4[(r0 + i) * 32 + (kk >> 2)];

            #pragma unroll
            for (int j = 0; j < 4; j++) {
                const ulonglong2 wA = *reinterpret_cast<const ulonglong2*>(
                    &Wsm[(kk + j) * OUT_F + n0]);
                const ulonglong2 wB = *reinterpret_cast<const ulonglong2*>(
                    &Wsm[(kk + j) * OUT_F + n0 + 4]);
                #pragma unroll
                for (int i = 0; i < 8; i++) {
                    const float a = (j == 0) ? h4[i].x : (j == 1) ? h4[i].y
                                  : (j == 2) ? h4[i].z : h4[i].w;
                    unsigned long long aa;
                    asm("mov.b64 %0, {%1, %1};" : "=l"(aa) : "f"(a));
                    asm("fma.rn.f32x2 %0, %1, %2, %0;" : "+l"(acc[i][0]) : "l"(aa), "l"(wA.x));
                    asm("fma.rn.f32x2 %0, %1, %2, %0;" : "+l"(acc[i][1]) : "l"(aa), "l"(wA.y));
                    asm("fma.rn.f32x2 %0, %1, %2, %0;" : "+l"(acc[i][2]) : "l"(aa), "l"(wB.x));
                    asm("fma.rn.f32x2 %0, %1, %2, %0;" : "+l"(acc[i][3]) : "l"(aa), "l"(wB.y));
                }
            }
        }

        const int m0 = tile * TILE_M;
        #pragma unroll
        for (int i = 0; i < 8; i++) {
            const int m = m0 + r0 + i;
            if (m < N_NODES) {
                float lo, hi;
                float o[8];
                #pragma unroll
                for (int j = 0; j < 4; j++) {
                    asm("mov.b64 {%0, %1}, %2;" : "=f"(lo), "=f"(hi) : "l"(acc[i][j]));
                    o[2 * j]     = lo + bb[2 * j];
                    o[2 * j + 1] = hi + bb[2 * j + 1];
                }
                float4* orow = reinterpret_cast<float4*>(out + (size_t)m * OUT_F + n0);
                orow[0] = make_float4(o[0], o[1], o[2], o[3]);
                orow[1] = make_float4(o[4], o[5], o[6], o[7]);
            }
        }
        __syncthreads();
    }
}

// ---------------------------------------------------------------------------
extern "C" void kernel_launch(void* const* d_in, const int* in_sizes, int n_in,
                              void* d_out, int out_size) {
    const float* x  = nullptr;
    const int*   ei = nullptr;
    const float* W  = nullptr;
    const float* b  = nullptr;

    for (int i = 0; i < n_in; i++) {
        switch (in_sizes[i]) {
            case N_NODES * IN_F:  x  = (const float*)d_in[i]; break;
            case 2 * N_EDGES:     ei = (const int*)d_in[i];   break;
            case OUT_F * IN_F:    W  = (const float*)d_in[i]; break;
            case OUT_F:           b  = (const float*)d_in[i]; break;
            default: break;
        }
    }

    float* out = (float*)d_out;

    void* cnt4_ptr = nullptr;
    cudaGetSymbolAddress(&cnt4_ptr, g_cnt4);
    cudaMemsetAsync(cnt4_ptr, 0, 4 * N_NODES * sizeof(int));

    hist_kernel<<<(N_EDGES / 4 + 255) / 256, 256>>>(ei);
    scanA_kernel<<<SCAN_B, SCAN_T>>>();
    scanB_kernel<<<SCAN_B, SCAN_T>>>();
    fill_kernel<<<(N_EDGES / 4 + 255) / 256, 256>>>(ei);

    // 2 nodes per warp -> 25000 warps -> 3125 blocks of 8 warps
    const int agg_blocks = ((N_NODES + 1) / 2 * 32 + 255) / 256;
    agg_kernel<<<agg_blocks, 256>>>(reinterpret_cast<const float4*>(x));

    const int smem_bytes = 3 * IN_F * OUT_F * (int)sizeof(float);  // 192KB
    cudaFuncSetAttribute(gemm_kernel, cudaFuncAttributeMaxDynamicSharedMemorySize,
                         smem_bytes);
    gemm_kernel<<<NUM_SM, 256, smem_bytes>>>(out, W, b);
}

// round 11
// speedup vs baseline: 1.0382x; 1.0382x over previous
#include <cuda_runtime.h>
#include <stdint.h>

#define N_NODES  50000
#define N_EDGES  800000
#define IN_F     128
#define OUT_F    128

#define SCAN_T   256
#define SCAN_B   ((N_NODES + SCAN_T - 1) / SCAN_T)   // 196

#define NUM_SM   148
#define TILE_M   128
#define N_TILES  ((N_NODES + TILE_M - 1) / TILE_M)   // 391

// -------------------- device scratch (no allocation allowed) ---------------
__device__ __align__(16) float g_agg[N_NODES * IN_F];  // normalized h rows
__device__ int   g_cnt4[4 * N_NODES];   // replicated histograms (stripe = edge%4)
__device__ int   g_base4[4 * N_NODES];  // per-(node,replica) bases; row0 = CSR start
__device__ int   g_cnt[N_NODES];        // per-node totals
__device__ __align__(16) int g_rank[N_EDGES];  // rank within (node,replica)
__device__ int   g_srcs[N_EDGES];       // edge sources grouped by dst
__device__ int   g_bsums[SCAN_B];
__device__ int   g_scan_done;           // grid-barrier counter (zeroed by hist)

// -------------------- 1) histogram (replicated) + rank capture -------------
__global__ void hist_kernel(const int* __restrict__ ei) {
    if (blockIdx.x == 0 && threadIdx.x == 0) g_scan_done = 0;  // reset barrier
    const int e4 = blockIdx.x * blockDim.x + threadIdx.x;
    if (e4 >= N_EDGES / 4) return;
    int4 d = reinterpret_cast<const int4*>(ei + N_EDGES)[e4];
    d.x = min(max(d.x, 0), N_NODES - 1);
    d.y = min(max(d.y, 0), N_NODES - 1);
    d.z = min(max(d.z, 0), N_NODES - 1);
    d.w = min(max(d.w, 0), N_NODES - 1);
    int4 r;
    r.x = atomicAdd(&g_cnt4[0 * N_NODES + d.x], 1);
    r.y = atomicAdd(&g_cnt4[1 * N_NODES + d.y], 1);
    r.z = atomicAdd(&g_cnt4[2 * N_NODES + d.z], 1);
    r.w = atomicAdd(&g_cnt4[3 * N_NODES + d.w], 1);
    reinterpret_cast<int4*>(g_rank)[e4] = r;
}

// -------------------- 2) fused exclusive scan (single kernel) --------------
// 196 blocks, all resident in wave 1 (grid << capacity) -> software grid
// barrier is deadlock-free. Phase 1: tile inclusive scan + publish block sum.
// Barrier. Phase 2: scan block sums, write bases.
__global__ void __launch_bounds__(SCAN_T)
scan_fused_kernel() {
    __shared__ int st[SCAN_T];
    __shared__ int sb[SCAN_T];
    const int tid = threadIdx.x;
    const int gid = blockIdx.x * SCAN_T + tid;

    int c0 = 0, c1 = 0, c2 = 0, tot = 0;
    if (gid < N_NODES) {
        c0 = g_cnt4[gid];
        c1 = g_cnt4[N_NODES + gid];
        c2 = g_cnt4[2 * N_NODES + gid];
        tot = c0 + c1 + c2 + g_cnt4[3 * N_NODES + gid];
        g_cnt[gid] = tot;
    }
    st[tid] = tot;
    __syncthreads();
    #pragma unroll
    for (int o = 1; o < SCAN_T; o <<= 1) {
        int t = (tid >= o) ? st[tid - o] : 0;
        __syncthreads();
        st[tid] += t;
        __syncthreads();
    }

    // publish block sum, arrive at grid barrier
    if (tid == 0) {
        g_bsums[blockIdx.x] = st[SCAN_T - 1];
        __threadfence();
        atomicAdd(&g_scan_done, 1);
    }
    // wait for all blocks
    if (tid == 0) {
        int v;
        do {
            asm volatile("ld.global.acquire.gpu.b32 %0, [%1];"
                         : "=r"(v) : "l"(&g_scan_done));
        } while (v < (int)gridDim.x);
    }
    __syncthreads();

    // phase 2: scan the 196 block sums (redundantly per block)
    int bv = (tid < SCAN_B) ? *(volatile int*)&g_bsums[tid] : 0;
    sb[tid] = bv;
    __syncthreads();
    #pragma unroll
    for (int o = 1; o < SCAN_T; o <<= 1) {
        int t = (tid >= o) ? sb[tid - o] : 0;
        __syncthreads();
        sb[tid] += t;
        __syncthreads();
    }
    const int base = (blockIdx.x > 0) ? sb[blockIdx.x - 1] : 0;

    if (gid < N_NODES) {
        const int excl = base + st[tid] - tot;   // exclusive scan value
        g_base4[gid]               = excl;       // row0 base == CSR row start
        g_base4[N_NODES + gid]     = excl + c0;
        g_base4[2 * N_NODES + gid] = excl + c0 + c1;
        g_base4[3 * N_NODES + gid] = excl + c0 + c1 + c2;
    }
}

// -------------------- 3) bucket-fill: NO atomics (base + rank) -------------
__global__ void fill_kernel(const int* __restrict__ ei) {
    const int e4 = blockIdx.x * blockDim.x + threadIdx.x;
    if (e4 >= N_EDGES / 4) return;
    int4 s = reinterpret_cast<const int4*>(ei)[e4];
    int4 d = reinterpret_cast<const int4*>(ei + N_EDGES)[e4];
    int4 r = reinterpret_cast<const int4*>(g_rank)[e4];
    s.x = min(max(s.x, 0), N_NODES - 1);
    s.y = min(max(s.y, 0), N_NODES - 1);
    s.z = min(max(s.z, 0), N_NODES - 1);
    s.w = min(max(s.w, 0), N_NODES - 1);
    d.x = min(max(d.x, 0), N_NODES - 1);
    d.y = min(max(d.y, 0), N_NODES - 1);
    d.z = min(max(d.z, 0), N_NODES - 1);
    d.w = min(max(d.w, 0), N_NODES - 1);
    const int p0 = g_base4[0 * N_NODES + d.x] + r.x;
    const int p1 = g_base4[1 * N_NODES + d.y] + r.y;
    const int p2 = g_base4[2 * N_NODES + d.z] + r.z;
    const int p3 = g_base4[3 * N_NODES + d.w] + r.w;
    g_srcs[p0] = s.x;
    g_srcs[p1] = s.y;
    g_srcs[p2] = s.z;
    g_srcs[p3] = s.w;
}

// -------------------- 4) gather-aggregate: one warp per node (R9) ----------
__global__ void __launch_bounds__(256)
agg_kernel(const float4* __restrict__ x4) {
    const int node = (blockIdx.x * blockDim.x + threadIdx.x) >> 5;
    if (node >= N_NODES) return;
    const int lane = threadIdx.x & 31;

    const int start = g_base4[node];   // row0 base == CSR row start
    const int cnt   = g_cnt[node];
    const int end   = start + cnt;

    float4 a0 = make_float4(0.f, 0.f, 0.f, 0.f);
    float4 a1 = make_float4(0.f, 0.f, 0.f, 0.f);
    float4 a2 = make_float4(0.f, 0.f, 0.f, 0.f);
    float4 a3 = make_float4(0.f, 0.f, 0.f, 0.f);

    int e = start;
    for (; e + 7 < end; e += 8) {
        int s0 = g_srcs[e],     s1 = g_srcs[e + 1];
        int s2 = g_srcs[e + 2], s3 = g_srcs[e + 3];
        int s4 = g_srcs[e + 4], s5 = g_srcs[e + 5];
        int s6 = g_srcs[e + 6], s7 = g_srcs[e + 7];
        float4 v0 = __ldg(&x4[s0 * 32 + lane]);
        float4 v1 = __ldg(&x4[s1 * 32 + lane]);
        float4 v2 = __ldg(&x4[s2 * 32 + lane]);
        float4 v3 = __ldg(&x4[s3 * 32 + lane]);
        float4 v4 = __ldg(&x4[s4 * 32 + lane]);
        float4 v5 = __ldg(&x4[s5 * 32 + lane]);
        float4 v6 = __ldg(&x4[s6 * 32 + lane]);
        float4 v7 = __ldg(&x4[s7 * 32 + lane]);
        a0.x += v0.x; a0.y += v0.y; a0.z += v0.z; a0.w += v0.w;
        a1.x += v1.x; a1.y += v1.y; a1.z += v1.z; a1.w += v1.w;
        a2.x += v2.x; a2.y += v2.y; a2.z += v2.z; a2.w += v2.w;
        a3.x += v3.x; a3.y += v3.y; a3.z += v3.z; a3.w += v3.w;
        a0.x += v4.x; a0.y += v4.y; a0.z += v4.z; a0.w += v4.w;
        a1.x += v5.x; a1.y += v5.y; a1.z += v5.z; a1.w += v5.w;
        a2.x += v6.x; a2.y += v6.y; a2.z += v6.z; a2.w += v6.w;
        a3.x += v7.x; a3.y += v7.y; a3.z += v7.z; a3.w += v7.w;
    }
    // predicated tail: up to 7 edges, all loads issue together (MLP=7)
    const int rem = end - e;
    if (rem > 0) {
        int idx[7];
        #pragma unroll
        for (int i = 0; i < 7; i++)
            idx[i] = (i < rem) ? g_srcs[e + i] : 0;
        float4 v[7];
        #pragma unroll
        for (int i = 0; i < 7; i++)
            if (i < rem) v[i] = __ldg(&x4[idx[i] * 32 + lane]);
        #pragma unroll
        for (int i = 0; i < 7; i++)
            if (i < rem) {
                float4* a = (i & 3) == 0 ? &a0 : (i & 3) == 1 ? &a1
                          : (i & 3) == 2 ? &a2 : &a3;
                a->x += v[i].x; a->y += v[i].y; a->z += v[i].z; a->w += v[i].w;
            }
    }

    const float inv = 1.0f / fmaxf((float)cnt, 1.0f);
    float4 r;
    r.x = (a0.x + a1.x + a2.x + a3.x) * inv;
    r.y = (a0.y + a1.y + a2.y + a3.y) * inv;
    r.z = (a0.z + a1.z + a2.z + a3.z) * inv;
    r.w = (a0.w + a1.w + a2.w + a3.w) * inv;
    reinterpret_cast<float4*>(g_agg)[(size_t)node * 32 + lane] = r;
}

// -------------------- 5) persistent double-buffered GEMM -------------------
__device__ __forceinline__ void issue_h_tile(int tile, float* buf, int tid) {
    const int m0 = tile * TILE_M;
    const float4* aggbase = reinterpret_cast<const float4*>(g_agg);
    #pragma unroll
    for (int j = 0; j < 16; j++) {
        const int i = tid + j * 256;
        const int r = i >> 5;
        const int c = i & 31;
        const int m = min(m0 + r, N_NODES - 1);
        const float4* src = aggbase + (size_t)m * 32 + c;
        unsigned saddr = (unsigned)__cvta_generic_to_shared(buf + i * 4);
        asm volatile("cp.async.cg.shared.global [%0], [%1], 16;"
                     :: "r"(saddr), "l"(src));
    }
    asm volatile("cp.async.commit_group;");
}

__global__ void __launch_bounds__(256, 1)
gemm_kernel(float* __restrict__ out, const float* __restrict__ W,
            const float* __restrict__ b) {
    extern __shared__ float sm[];
    float* Wsm   = sm;
    float* Hbuf0 = sm + IN_F * OUT_F;
    float* Hbuf1 = Hbuf0 + TILE_M * IN_F;

    const int tid = threadIdx.x;

    int tile0 = blockIdx.x;
    if (tile0 < N_TILES) issue_h_tile(tile0, Hbuf0, tid);

    #pragma unroll 4
    for (int i = tid; i < OUT_F * IN_F; i += 256) {
        const int n = i >> 7;
        const int k = i & 127;
        Wsm[k * OUT_F + n] = W[i];
    }

    const int rowg = tid >> 4;
    const int colg = tid & 15;
    const int r0   = rowg * 8;
    const int n0   = colg * 8;

    float bb[8];
    #pragma unroll
    for (int j = 0; j < 8; j++) bb[j] = b[n0 + j];

    int it = 0;
    for (int tile = blockIdx.x; tile < N_TILES; tile += NUM_SM, it++) {
        float* cur = (it & 1) ? Hbuf1 : Hbuf0;
        float* nxt = (it & 1) ? Hbuf0 : Hbuf1;
        const int ntile = tile + NUM_SM;
        if (ntile < N_TILES) {
            issue_h_tile(ntile, nxt, tid);
            asm volatile("cp.async.wait_group 1;");
        } else {
            asm volatile("cp.async.wait_group 0;");
        }
        __syncthreads();

        const float4* Hsm4 = reinterpret_cast<const float4*>(cur);

        unsigned long long acc[8][4];
        #pragma unroll
        for (int i = 0; i < 8; i++)
            #pragma unroll
            for (int j = 0; j < 4; j++) acc[i][j] = 0ULL;

        for (int kk = 0; kk < IN_F; kk += 4) {
            float4 h4[8];
            #pragma unroll
            for (int i = 0; i < 8; i++)
                h4[i] = Hsm4[(r0 + i) * 32 + (kk >> 2)];

            #pragma unroll
            for (int j = 0; j < 4; j++) {
                const ulonglong2 wA = *reinterpret_cast<const ulonglong2*>(
                    &Wsm[(kk + j) * OUT_F + n0]);
                const ulonglong2 wB = *reinterpret_cast<const ulonglong2*>(
                    &Wsm[(kk + j) * OUT_F + n0 + 4]);
                #pragma unroll
                for (int i = 0; i < 8; i++) {
                    const float a = (j == 0) ? h4[i].x : (j == 1) ? h4[i].y
                                  : (j == 2) ? h4[i].z : h4[i].w;
                    unsigned long long aa;
                    asm("mov.b64 %0, {%1, %1};" : "=l"(aa) : "f"(a));
                    asm("fma.rn.f32x2 %0, %1, %2, %0;" : "+l"(acc[i][0]) : "l"(aa), "l"(wA.x));
                    asm("fma.rn.f32x2 %0, %1, %2, %0;" : "+l"(acc[i][1]) : "l"(aa), "l"(wA.y));
                    asm("fma.rn.f32x2 %0, %1, %2, %0;" : "+l"(acc[i][2]) : "l"(aa), "l"(wB.x));
                    asm("fma.rn.f32x2 %0, %1, %2, %0;" : "+l"(acc[i][3]) : "l"(aa), "l"(wB.y));
                }
            }
        }

        const int m0 = tile * TILE_M;
        #pragma unroll
        for (int i = 0; i < 8; i++) {
            const int m = m0 + r0 + i;
            if (m < N_NODES) {
                float lo, hi;
                float o[8];
                #pragma unroll
                for (int j = 0; j < 4; j++) {
                    asm("mov.b64 {%0, %1}, %2;" : "=f"(lo), "=f"(hi) : "l"(acc[i][j]));
                    o[2 * j]     = lo + bb[2 * j];
                    o[2 * j + 1] = hi + bb[2 * j + 1];
                }
                float4* orow = reinterpret_cast<float4*>(out + (size_t)m * OUT_F + n0);
                orow[0] = make_float4(o[0], o[1], o[2], o[3]);
                orow[1] = make_float4(o[4], o[5], o[6], o[7]);
            }
        }
        __syncthreads();
    }
}

// ---------------------------------------------------------------------------
extern "C" void kernel_launch(void* const* d_in, const int* in_sizes, int n_in,
                              void* d_out, int out_size) {
    const float* x  = nullptr;
    const int*   ei = nullptr;
    const float* W  = nullptr;
    const float* b  = nullptr;

    for (int i = 0; i < n_in; i++) {
        switch (in_sizes[i]) {
            case N_NODES * IN_F:  x  = (const float*)d_in[i]; break;
            case 2 * N_EDGES:     ei = (const int*)d_in[i];   break;
            case OUT_F * IN_F:    W  = (const float*)d_in[i]; break;
            case OUT_F:           b  = (const float*)d_in[i]; break;
            default: break;
        }
    }

    float* out = (float*)d_out;

    void* cnt4_ptr = nullptr;
    cudaGetSymbolAddress(&cnt4_ptr, g_cnt4);
    cudaMemsetAsync(cnt4_ptr, 0, 4 * N_NODES * sizeof(int));

    hist_kernel<<<(N_EDGES / 4 + 255) / 256, 256>>>(ei);
    scan_fused_kernel<<<SCAN_B, SCAN_T>>>();
    fill_kernel<<<(N_EDGES / 4 + 255) / 256, 256>>>(ei);

    const int agg_blocks = (N_NODES * 32 + 255) / 256;   // 6250
    agg_kernel<<<agg_blocks, 256>>>(reinterpret_cast<const float4*>(x));

    const int smem_bytes = 3 * IN_F * OUT_F * (int)sizeof(float);  // 192KB
    cudaFuncSetAttribute(gemm_kernel, cudaFuncAttributeMaxDynamicSharedMemorySize,
                         smem_bytes);
    gemm_kernel<<<NUM_SM, 256, smem_bytes>>>(out, W, b);
}

// round 12
// speedup vs baseline: 1.0566x; 1.0177x over previous
#include <cuda_runtime.h>
#include <stdint.h>

#define N_NODES  50000
#define N_EDGES  800000
#define IN_F     128
#define OUT_F    128

#define SCAN_T   256
#define SCAN_B   ((N_NODES + SCAN_T - 1) / SCAN_T)   // 196

#define NUM_SM   148
#define TILE_M   128
#define N_TILES  ((N_NODES + TILE_M - 1) / TILE_M)   // 391

// -------------------- device scratch (no allocation allowed) ---------------
__device__ __align__(16) float g_agg[N_NODES * IN_F];  // normalized h rows
__device__ int   g_cnt4[4 * N_NODES];   // replicated histograms (stripe = edge%4)
__device__ int   g_base4[4 * N_NODES];  // per-(node,replica) bases; row0 = CSR start
__device__ int   g_cnt[N_NODES];        // per-node totals
__device__ __align__(16) int g_rank[N_EDGES];  // rank within (node,replica)
__device__ int   g_srcs[N_EDGES];       // edge sources grouped by dst
__device__ int   g_bsums[SCAN_B];
__device__ int   g_scan_done;           // grid-barrier counter (zeroed by hist)

// -------------------- 1) histogram (replicated) + rank capture -------------
__global__ void hist_kernel(const int* __restrict__ ei) {
    if (blockIdx.x == 0 && threadIdx.x == 0) g_scan_done = 0;  // reset barrier
    const int e4 = blockIdx.x * blockDim.x + threadIdx.x;
    if (e4 >= N_EDGES / 4) return;
    int4 d = reinterpret_cast<const int4*>(ei + N_EDGES)[e4];
    d.x = min(max(d.x, 0), N_NODES - 1);
    d.y = min(max(d.y, 0), N_NODES - 1);
    d.z = min(max(d.z, 0), N_NODES - 1);
    d.w = min(max(d.w, 0), N_NODES - 1);
    int4 r;
    r.x = atomicAdd(&g_cnt4[0 * N_NODES + d.x], 1);
    r.y = atomicAdd(&g_cnt4[1 * N_NODES + d.y], 1);
    r.z = atomicAdd(&g_cnt4[2 * N_NODES + d.z], 1);
    r.w = atomicAdd(&g_cnt4[3 * N_NODES + d.w], 1);
    reinterpret_cast<int4*>(g_rank)[e4] = r;
}

// -------------------- 2) fused exclusive scan (single kernel) --------------
__global__ void __launch_bounds__(SCAN_T)
scan_fused_kernel() {
    __shared__ int st[SCAN_T];
    __shared__ int sb[SCAN_T];
    const int tid = threadIdx.x;
    const int gid = blockIdx.x * SCAN_T + tid;

    int c0 = 0, c1 = 0, c2 = 0, tot = 0;
    if (gid < N_NODES) {
        c0 = g_cnt4[gid];
        c1 = g_cnt4[N_NODES + gid];
        c2 = g_cnt4[2 * N_NODES + gid];
        tot = c0 + c1 + c2 + g_cnt4[3 * N_NODES + gid];
        g_cnt[gid] = tot;
    }
    st[tid] = tot;
    __syncthreads();
    #pragma unroll
    for (int o = 1; o < SCAN_T; o <<= 1) {
        int t = (tid >= o) ? st[tid - o] : 0;
        __syncthreads();
        st[tid] += t;
        __syncthreads();
    }

    if (tid == 0) {
        g_bsums[blockIdx.x] = st[SCAN_T - 1];
        __threadfence();
        atomicAdd(&g_scan_done, 1);
    }
    if (tid == 0) {
        int v;
        do {
            asm volatile("ld.global.acquire.gpu.b32 %0, [%1];"
                         : "=r"(v) : "l"(&g_scan_done));
        } while (v < (int)gridDim.x);
    }
    __syncthreads();

    int bv = (tid < SCAN_B) ? *(volatile int*)&g_bsums[tid] : 0;
    sb[tid] = bv;
    __syncthreads();
    #pragma unroll
    for (int o = 1; o < SCAN_T; o <<= 1) {
        int t = (tid >= o) ? sb[tid - o] : 0;
        __syncthreads();
        sb[tid] += t;
        __syncthreads();
    }
    const int base = (blockIdx.x > 0) ? sb[blockIdx.x - 1] : 0;

    if (gid < N_NODES) {
        const int excl = base + st[tid] - tot;
        g_base4[gid]               = excl;       // row0 base == CSR row start
        g_base4[N_NODES + gid]     = excl + c0;
        g_base4[2 * N_NODES + gid] = excl + c0 + c1;
        g_base4[3 * N_NODES + gid] = excl + c0 + c1 + c2;
    }
}

// -------------------- 3) bucket-fill: NO atomics (base + rank) -------------
__global__ void fill_kernel(const int* __restrict__ ei) {
    const int e4 = blockIdx.x * blockDim.x + threadIdx.x;
    if (e4 >= N_EDGES / 4) return;
    int4 s = reinterpret_cast<const int4*>(ei)[e4];
    int4 d = reinterpret_cast<const int4*>(ei + N_EDGES)[e4];
    int4 r = reinterpret_cast<const int4*>(g_rank)[e4];
    s.x = min(max(s.x, 0), N_NODES - 1);
    s.y = min(max(s.y, 0), N_NODES - 1);
    s.z = min(max(s.z, 0), N_NODES - 1);
    s.w = min(max(s.w, 0), N_NODES - 1);
    d.x = min(max(d.x, 0), N_NODES - 1);
    d.y = min(max(d.y, 0), N_NODES - 1);
    d.z = min(max(d.z, 0), N_NODES - 1);
    d.w = min(max(d.w, 0), N_NODES - 1);
    const int p0 = g_base4[0 * N_NODES + d.x] + r.x;
    const int p1 = g_base4[1 * N_NODES + d.y] + r.y;
    const int p2 = g_base4[2 * N_NODES + d.z] + r.z;
    const int p3 = g_base4[3 * N_NODES + d.w] + r.w;
    g_srcs[p0] = s.x;
    g_srcs[p1] = s.y;
    g_srcs[p2] = s.z;
    g_srcs[p3] = s.w;
}

// -------------------- 4) gather-aggregate: one warp per node ---------------
// MLP-8 gathers; TWO accumulators (regs 58 -> ~50); launch_bounds(256,5)
// caps at 51 regs -> 40 warps/SM (62.5% occ) vs previous 32 (50%).
__global__ void __launch_bounds__(256, 5)
agg_kernel(const float4* __restrict__ x4) {
    const int node = (blockIdx.x * blockDim.x + threadIdx.x) >> 5;
    if (node >= N_NODES) return;
    const int lane = threadIdx.x & 31;

    const int start = g_base4[node];   // row0 base == CSR row start
    const int cnt   = g_cnt[node];
    const int end   = start + cnt;

    float4 a0 = make_float4(0.f, 0.f, 0.f, 0.f);
    float4 a1 = make_float4(0.f, 0.f, 0.f, 0.f);

    int e = start;
    for (; e + 7 < end; e += 8) {
        int s0 = g_srcs[e],     s1 = g_srcs[e + 1];
        int s2 = g_srcs[e + 2], s3 = g_srcs[e + 3];
        int s4 = g_srcs[e + 4], s5 = g_srcs[e + 5];
        int s6 = g_srcs[e + 6], s7 = g_srcs[e + 7];
        float4 v0 = __ldg(&x4[s0 * 32 + lane]);
        float4 v1 = __ldg(&x4[s1 * 32 + lane]);
        float4 v2 = __ldg(&x4[s2 * 32 + lane]);
        float4 v3 = __ldg(&x4[s3 * 32 + lane]);
        float4 v4 = __ldg(&x4[s4 * 32 + lane]);
        float4 v5 = __ldg(&x4[s5 * 32 + lane]);
        float4 v6 = __ldg(&x4[s6 * 32 + lane]);
        float4 v7 = __ldg(&x4[s7 * 32 + lane]);
        a0.x += v0.x; a0.y += v0.y; a0.z += v0.z; a0.w += v0.w;
        a1.x += v1.x; a1.y += v1.y; a1.z += v1.z; a1.w += v1.w;
        a0.x += v2.x; a0.y += v2.y; a0.z += v2.z; a0.w += v2.w;
        a1.x += v3.x; a1.y += v3.y; a1.z += v3.z; a1.w += v3.w;
        a0.x += v4.x; a0.y += v4.y; a0.z += v4.z; a0.w += v4.w;
        a1.x += v5.x; a1.y += v5.y; a1.z += v5.z; a1.w += v5.w;
        a0.x += v6.x; a0.y += v6.y; a0.z += v6.z; a0.w += v6.w;
        a1.x += v7.x; a1.y += v7.y; a1.z += v7.z; a1.w += v7.w;
    }
    // predicated tail: up to 7 edges, all loads issue together (MLP=7)
    const int rem = end - e;
    if (rem > 0) {
        int idx[7];
        #pragma unroll
        for (int i = 0; i < 7; i++)
            idx[i] = (i < rem) ? g_srcs[e + i] : 0;
        float4 v[7];
        #pragma unroll
        for (int i = 0; i < 7; i++)
            if (i < rem) v[i] = __ldg(&x4[idx[i] * 32 + lane]);
        #pragma unroll
        for (int i = 0; i < 7; i++)
            if (i < rem) {
                float4* a = (i & 1) ? &a1 : &a0;
                a->x += v[i].x; a->y += v[i].y; a->z += v[i].z; a->w += v[i].w;
            }
    }

    const float inv = 1.0f / fmaxf((float)cnt, 1.0f);
    float4 r;
    r.x = (a0.x + a1.x) * inv;
    r.y = (a0.y + a1.y) * inv;
    r.z = (a0.z + a1.z) * inv;
    r.w = (a0.w + a1.w) * inv;
    reinterpret_cast<float4*>(g_agg)[(size_t)node * 32 + lane] = r;
}

// -------------------- 5) persistent double-buffered GEMM -------------------
__device__ __forceinline__ void issue_h_tile(int tile, float* buf, int tid) {
    const int m0 = tile * TILE_M;
    const float4* aggbase = reinterpret_cast<const float4*>(g_agg);
    #pragma unroll
    for (int j = 0; j < 16; j++) {
        const int i = tid + j * 256;
        const int r = i >> 5;
        const int c = i & 31;
        const int m = min(m0 + r, N_NODES - 1);
        const float4* src = aggbase + (size_t)m * 32 + c;
        unsigned saddr = (unsigned)__cvta_generic_to_shared(buf + i * 4);
        asm volatile("cp.async.cg.shared.global [%0], [%1], 16;"
                     :: "r"(saddr), "l"(src));
    }
    asm volatile("cp.async.commit_group;");
}

__global__ void __launch_bounds__(256, 1)
gemm_kernel(float* __restrict__ out, const float* __restrict__ W,
            const float* __restrict__ b) {
    extern __shared__ float sm[];
    float* Wsm   = sm;
    float* Hbuf0 = sm + IN_F * OUT_F;
    float* Hbuf1 = Hbuf0 + TILE_M * IN_F;

    const int tid = threadIdx.x;

    int tile0 = blockIdx.x;
    if (tile0 < N_TILES) issue_h_tile(tile0, Hbuf0, tid);

    #pragma unroll 4
    for (int i = tid; i < OUT_F * IN_F; i += 256) {
        const int n = i >> 7;
        const int k = i & 127;
        Wsm[k * OUT_F + n] = W[i];
    }

    const int rowg = tid >> 4;
    const int colg = tid & 15;
    const int r0   = rowg * 8;
    const int n0   = colg * 8;

    float bb[8];
    #pragma unroll
    for (int j = 0; j < 8; j++) bb[j] = b[n0 + j];

    int it = 0;
    for (int tile = blockIdx.x; tile < N_TILES; tile += NUM_SM, it++) {
        float* cur = (it & 1) ? Hbuf1 : Hbuf0;
        float* nxt = (it & 1) ? Hbuf0 : Hbuf1;
        const int ntile = tile + NUM_SM;
        if (ntile < N_TILES) {
            issue_h_tile(ntile, nxt, tid);
            asm volatile("cp.async.wait_group 1;");
        } else {
            asm volatile("cp.async.wait_group 0;");
        }
        __syncthreads();

        const float4* Hsm4 = reinterpret_cast<const float4*>(cur);

        unsigned long long acc[8][4];
        #pragma unroll
        for (int i = 0; i < 8; i++)
            #pragma unroll
            for (int j = 0; j < 4; j++) acc[i][j] = 0ULL;

        for (int kk = 0; kk < IN_F; kk += 4) {
            float4 h4[8];
            #pragma unroll
            for (int i = 0; i < 8; i++)
                h4[i] = Hsm4[(r0 + i) * 32 + (kk >> 2)];

            #pragma unroll
            for (int j = 0; j < 4; j++) {
                const ulonglong2 wA = *reinterpret_cast<const ulonglong2*>(
                    &Wsm[(kk + j) * OUT_F + n0]);
                const ulonglong2 wB = *reinterpret_cast<const ulonglong2*>(
                    &Wsm[(kk + j) * OUT_F + n0 + 4]);
                #pragma unroll
                for (int i = 0; i < 8; i++) {
                    const float a = (j == 0) ? h4[i].x : (j == 1) ? h4[i].y
                                  : (j == 2) ? h4[i].z : h4[i].w;
                    unsigned long long aa;
                    asm("mov.b64 %0, {%1, %1};" : "=l"(aa) : "f"(a));
                    asm("fma.rn.f32x2 %0, %1, %2, %0;" : "+l"(acc[i][0]) : "l"(aa), "l"(wA.x));
                    asm("fma.rn.f32x2 %0, %1, %2, %0;" : "+l"(acc[i][1]) : "l"(aa), "l"(wA.y));
                    asm("fma.rn.f32x2 %0, %1, %2, %0;" : "+l"(acc[i][2]) : "l"(aa), "l"(wB.x));
                    asm("fma.rn.f32x2 %0, %1, %2, %0;" : "+l"(acc[i][3]) : "l"(aa), "l"(wB.y));
                }
            }
        }

        const int m0 = tile * TILE_M;
        #pragma unroll
        for (int i = 0; i < 8; i++) {
            const int m = m0 + r0 + i;
            if (m < N_NODES) {
                float lo, hi;
                float o[8];
                #pragma unroll
                for (int j = 0; j < 4; j++) {
                    asm("mov.b64 {%0, %1}, %2;" : "=f"(lo), "=f"(hi) : "l"(acc[i][j]));
                    o[2 * j]     = lo + bb[2 * j];
                    o[2 * j + 1] = hi + bb[2 * j + 1];
                }
                float4* orow = reinterpret_cast<float4*>(out + (size_t)m * OUT_F + n0);
                orow[0] = make_float4(o[0], o[1], o[2], o[3]);
                orow[1] = make_float4(o[4], o[5], o[6], o[7]);
            }
        }
        __syncthreads();
    }
}

// ---------------------------------------------------------------------------
extern "C" void kernel_launch(void* const* d_in, const int* in_sizes, int n_in,
                              void* d_out, int out_size) {
    const float* x  = nullptr;
    const int*   ei = nullptr;
    const float* W  = nullptr;
    const float* b  = nullptr;

    for (int i = 0; i < n_in; i++) {
        switch (in_sizes[i]) {
            case N_NODES * IN_F:  x  = (const float*)d_in[i]; break;
            case 2 * N_EDGES:     ei = (const int*)d_in[i];   break;
            case OUT_F * IN_F:    W  = (const float*)d_in[i]; break;
            case OUT_F:           b  = (const float*)d_in[i]; break;
            default: break;
        }
    }

    float* out = (float*)d_out;

    void* cnt4_ptr = nullptr;
    cudaGetSymbolAddress(&cnt4_ptr, g_cnt4);
    cudaMemsetAsync(cnt4_ptr, 0, 4 * N_NODES * sizeof(int));

    hist_kernel<<<(N_EDGES / 4 + 255) / 256, 256>>>(ei);
    scan_fused_kernel<<<SCAN_B, SCAN_T>>>();
    fill_kernel<<<(N_EDGES / 4 + 255) / 256, 256>>>(ei);

    const int agg_blocks = (N_NODES * 32 + 255) / 256;   // 6250
    agg_kernel<<<agg_blocks, 256>>>(reinterpret_cast<const float4*>(x));

    const int smem_bytes = 3 * IN_F * OUT_F * (int)sizeof(float);  // 192KB
    cudaFuncSetAttribute(gemm_kernel, cudaFuncAttributeMaxDynamicSharedMemorySize,
                         smem_bytes);
    gemm_kernel<<<NUM_SM, 256, smem_bytes>>>(out, W, b);
}

// round 13
// speedup vs baseline: 1.0597x; 1.0030x over previous
#include <cuda_runtime.h>
#include <cuda_fp16.h>
#include <stdint.h>

#define N_NODES  50000
#define N_EDGES  800000
#define IN_F     128
#define OUT_F    128

#define SCAN_T   256
#define SCAN_B   ((N_NODES + SCAN_T - 1) / SCAN_T)   // 196

#define NUM_SM   148
#define TILE_M   128
#define N_TILES  ((N_NODES + TILE_M - 1) / TILE_M)   // 391

#define HIST_BLOCKS ((N_EDGES / 4 + 255) / 256)      // 782

// -------------------- device scratch (no allocation allowed) ---------------
__device__ __align__(16) float  g_agg[N_NODES * IN_F];  // normalized h rows (fp32)
__device__ __align__(16) __half g_xh[N_NODES * IN_F];   // fp16 copy of x
__device__ int   g_cnt4[4 * N_NODES];   // replicated histograms (stripe = edge%4)
__device__ int   g_base4[4 * N_NODES];  // per-(node,replica) bases; row0 = CSR start
__device__ int   g_cnt[N_NODES];        // per-node totals
__device__ __align__(16) int g_rank[N_EDGES];  // rank within (node,replica)
__device__ int   g_srcs[N_EDGES];       // edge sources grouped by dst
__device__ int   g_bsums[SCAN_B];
__device__ int   g_scan_done;           // grid-barrier counter (reset here each call)

// -------------------- 1) histogram + rank capture + x->fp16 convert --------
// The convert loop's bandwidth work overlaps the atomics' latency.
__global__ void __launch_bounds__(256)
hist_kernel(const int* __restrict__ ei, const float4* __restrict__ x4) {
    const int gtid = blockIdx.x * blockDim.x + threadIdx.x;
    if (gtid == 0) g_scan_done = 0;   // reset grid barrier for scan kernel

    // ---- histogram part: 4 edges/thread, replicated counters, keep ranks
    int4 r;
    const int e4 = gtid;
    const bool do_hist = (e4 < N_EDGES / 4);
    if (do_hist) {
        int4 d = reinterpret_cast<const int4*>(ei + N_EDGES)[e4];
        d.x = min(max(d.x, 0), N_NODES - 1);
        d.y = min(max(d.y, 0), N_NODES - 1);
        d.z = min(max(d.z, 0), N_NODES - 1);
        d.w = min(max(d.w, 0), N_NODES - 1);
        r.x = atomicAdd(&g_cnt4[0 * N_NODES + d.x], 1);
        r.y = atomicAdd(&g_cnt4[1 * N_NODES + d.y], 1);
        r.z = atomicAdd(&g_cnt4[2 * N_NODES + d.z], 1);
        r.w = atomicAdd(&g_cnt4[3 * N_NODES + d.w], 1);
    }

    // ---- convert part: x (fp32) -> g_xh (fp16), grid-stride
    {
        const int stride = gridDim.x * blockDim.x;     // 200192
        uint2* xh2 = reinterpret_cast<uint2*>(g_xh);
        const int n4 = N_NODES * IN_F / 4;             // 1.6M
        for (int i = gtid; i < n4; i += stride) {
            float4 v = x4[i];
            __half2 h0 = __floats2half2_rn(v.x, v.y);
            __half2 h1 = __floats2half2_rn(v.z, v.w);
            uint2 p;
            p.x = *reinterpret_cast<unsigned*>(&h0);
            p.y = *reinterpret_cast<unsigned*>(&h1);
            xh2[i] = p;
        }
    }

    if (do_hist)
        reinterpret_cast<int4*>(g_rank)[e4] = r;   // contiguous store
}

// -------------------- 2) fused exclusive scan (single kernel) --------------
__global__ void __launch_bounds__(SCAN_T)
scan_fused_kernel() {
    __shared__ int st[SCAN_T];
    __shared__ int sb[SCAN_T];
    const int tid = threadIdx.x;
    const int gid = blockIdx.x * SCAN_T + tid;

    int c0 = 0, c1 = 0, c2 = 0, tot = 0;
    if (gid < N_NODES) {
        c0 = g_cnt4[gid];
        c1 = g_cnt4[N_NODES + gid];
        c2 = g_cnt4[2 * N_NODES + gid];
        tot = c0 + c1 + c2 + g_cnt4[3 * N_NODES + gid];
        g_cnt[gid] = tot;
    }
    st[tid] = tot;
    __syncthreads();
    #pragma unroll
    for (int o = 1; o < SCAN_T; o <<= 1) {
        int t = (tid >= o) ? st[tid - o] : 0;
        __syncthreads();
        st[tid] += t;
        __syncthreads();
    }

    if (tid == 0) {
        g_bsums[blockIdx.x] = st[SCAN_T - 1];
        __threadfence();
        atomicAdd(&g_scan_done, 1);
    }
    if (tid == 0) {
        int v;
        do {
            asm volatile("ld.global.acquire.gpu.b32 %0, [%1];"
                         : "=r"(v) : "l"(&g_scan_done));
        } while (v < (int)gridDim.x);
    }
    __syncthreads();

    int bv = (tid < SCAN_B) ? *(volatile int*)&g_bsums[tid] : 0;
    sb[tid] = bv;
    __syncthreads();
    #pragma unroll
    for (int o = 1; o < SCAN_T; o <<= 1) {
        int t = (tid >= o) ? sb[tid - o] : 0;
        __syncthreads();
        sb[tid] += t;
        __syncthreads();
    }
    const int base = (blockIdx.x > 0) ? sb[blockIdx.x - 1] : 0;

    if (gid < N_NODES) {
        const int excl = base + st[tid] - tot;
        g_base4[gid]               = excl;       // row0 base == CSR row start
        g_base4[N_NODES + gid]     = excl + c0;
        g_base4[2 * N_NODES + gid] = excl + c0 + c1;
        g_base4[3 * N_NODES + gid] = excl + c0 + c1 + c2;
    }
}

// -------------------- 3) bucket-fill: NO atomics (base + rank) -------------
__global__ void fill_kernel(const int* __restrict__ ei) {
    const int e4 = blockIdx.x * blockDim.x + threadIdx.x;
    if (e4 >= N_EDGES / 4) return;
    int4 s = reinterpret_cast<const int4*>(ei)[e4];
    int4 d = reinterpret_cast<const int4*>(ei + N_EDGES)[e4];
    int4 r = reinterpret_cast<const int4*>(g_rank)[e4];
    s.x = min(max(s.x, 0), N_NODES - 1);
    s.y = min(max(s.y, 0), N_NODES - 1);
    s.z = min(max(s.z, 0), N_NODES - 1);
    s.w = min(max(s.w, 0), N_NODES - 1);
    d.x = min(max(d.x, 0), N_NODES - 1);
    d.y = min(max(d.y, 0), N_NODES - 1);
    d.z = min(max(d.z, 0), N_NODES - 1);
    d.w = min(max(d.w, 0), N_NODES - 1);
    const int p0 = g_base4[0 * N_NODES + d.x] + r.x;
    const int p1 = g_base4[1 * N_NODES + d.y] + r.y;
    const int p2 = g_base4[2 * N_NODES + d.z] + r.z;
    const int p3 = g_base4[3 * N_NODES + d.w] + r.w;
    g_srcs[p0] = s.x;
    g_srcs[p1] = s.y;
    g_srcs[p2] = s.z;
    g_srcs[p3] = s.w;
}

// -------------------- 4) gather-aggregate: fp16 source, fp32 accumulate ----
// One warp per node, lane covers 4 features = one uint2 (2 half2) per edge.
// MLP-8; data regs halved vs fp32 -> higher occupancy (6 blocks/SM).
__device__ __forceinline__ void acc_h2(float4& a, uint2 p) {
    __half2 h0 = *reinterpret_cast<__half2*>(&p.x);
    __half2 h1 = *reinterpret_cast<__half2*>(&p.y);
    float2 f0 = __half22float2(h0);
    float2 f1 = __half22float2(h1);
    a.x += f0.x; a.y += f0.y; a.z += f1.x; a.w += f1.y;
}

__global__ void __launch_bounds__(256, 6)
agg_kernel() {
    const int node = (blockIdx.x * blockDim.x + threadIdx.x) >> 5;
    if (node >= N_NODES) return;
    const int lane = threadIdx.x & 31;

    const int start = g_base4[node];   // row0 base == CSR row start
    const int cnt   = g_cnt[node];
    const int end   = start + cnt;

    const uint2* xh2 = reinterpret_cast<const uint2*>(g_xh);

    float4 a0 = make_float4(0.f, 0.f, 0.f, 0.f);
    float4 a1 = make_float4(0.f, 0.f, 0.f, 0.f);

    int e = start;
    for (; e + 7 < end; e += 8) {
        int s0 = g_srcs[e],     s1 = g_srcs[e + 1];
        int s2 = g_srcs[e + 2], s3 = g_srcs[e + 3];
        int s4 = g_srcs[e + 4], s5 = g_srcs[e + 5];
        int s6 = g_srcs[e + 6], s7 = g_srcs[e + 7];
        uint2 p0 = __ldg(&xh2[s0 * 32 + lane]);
        uint2 p1 = __ldg(&xh2[s1 * 32 + lane]);
        uint2 p2 = __ldg(&xh2[s2 * 32 + lane]);
        uint2 p3 = __ldg(&xh2[s3 * 32 + lane]);
        uint2 p4 = __ldg(&xh2[s4 * 32 + lane]);
        uint2 p5 = __ldg(&xh2[s5 * 32 + lane]);
        uint2 p6 = __ldg(&xh2[s6 * 32 + lane]);
        uint2 p7 = __ldg(&xh2[s7 * 32 + lane]);
        acc_h2(a0, p0); acc_h2(a1, p1); acc_h2(a0, p2); acc_h2(a1, p3);
        acc_h2(a0, p4); acc_h2(a1, p5); acc_h2(a0, p6); acc_h2(a1, p7);
    }
    // predicated tail: up to 7 edges, all loads issue together (MLP=7)
    const int rem = end - e;
    if (rem > 0) {
        int idx[7];
        #pragma unroll
        for (int i = 0; i < 7; i++)
            idx[i] = (i < rem) ? g_srcs[e + i] : 0;
        uint2 v[7];
        #pragma unroll
        for (int i = 0; i < 7; i++)
            if (i < rem) v[i] = __ldg(&xh2[idx[i] * 32 + lane]);
        #pragma unroll
        for (int i = 0; i < 7; i++)
            if (i < rem) {
                if (i & 1) acc_h2(a1, v[i]); else acc_h2(a0, v[i]);
            }
    }

    const float inv = 1.0f / fmaxf((float)cnt, 1.0f);
    float4 r;
    r.x = (a0.x + a1.x) * inv;
    r.y = (a0.y + a1.y) * inv;
    r.z = (a0.z + a1.z) * inv;
    r.w = (a0.w + a1.w) * inv;
    reinterpret_cast<float4*>(g_agg)[(size_t)node * 32 + lane] = r;
}

// -------------------- 5) persistent double-buffered GEMM -------------------
__device__ __forceinline__ void issue_h_tile(int tile, float* buf, int tid) {
    const int m0 = tile * TILE_M;
    const float4* aggbase = reinterpret_cast<const float4*>(g_agg);
    #pragma unroll
    for (int j = 0; j < 16; j++) {
        const int i = tid + j * 256;
        const int r = i >> 5;
        const int c = i & 31;
        const int m = min(m0 + r, N_NODES - 1);
        const float4* src = aggbase + (size_t)m * 32 + c;
        unsigned saddr = (unsigned)__cvta_generic_to_shared(buf + i * 4);
        asm volatile("cp.async.cg.shared.global [%0], [%1], 16;"
                     :: "r"(saddr), "l"(src));
    }
    asm volatile("cp.async.commit_group;");
}

__global__ void __launch_bounds__(256, 1)
gemm_kernel(float* __restrict__ out, const float* __restrict__ W,
            const float* __restrict__ b) {
    extern __shared__ float sm[];
    float* Wsm   = sm;
    float* Hbuf0 = sm + IN_F * OUT_F;
    float* Hbuf1 = Hbuf0 + TILE_M * IN_F;

    const int tid = threadIdx.x;

    int tile0 = blockIdx.x;
    if (tile0 < N_TILES) issue_h_tile(tile0, Hbuf0, tid);

    #pragma unroll 4
    for (int i = tid; i < OUT_F * IN_F; i += 256) {
        const int n = i >> 7;
        const int k = i & 127;
        Wsm[k * OUT_F + n] = W[i];
    }

    const int rowg = tid >> 4;
    const int colg = tid & 15;
    const int r0   = rowg * 8;
    const int n0   = colg * 8;

    float bb[8];
    #pragma unroll
    for (int j = 0; j < 8; j++) bb[j] = b[n0 + j];

    int it = 0;
    for (int tile = blockIdx.x; tile < N_TILES; tile += NUM_SM, it++) {
        float* cur = (it & 1) ? Hbuf1 : Hbuf0;
        float* nxt = (it & 1) ? Hbuf0 : Hbuf1;
        const int ntile = tile + NUM_SM;
        if (ntile < N_TILES) {
            issue_h_tile(ntile, nxt, tid);
            asm volatile("cp.async.wait_group 1;");
        } else {
            asm volatile("cp.async.wait_group 0;");
        }
        __syncthreads();

        const float4* Hsm4 = reinterpret_cast<const float4*>(cur);

        unsigned long long acc[8][4];
        #pragma unroll
        for (int i = 0; i < 8; i++)
            #pragma unroll
            for (int j = 0; j < 4; j++) acc[i][j] = 0ULL;

        for (int kk = 0; kk < IN_F; kk += 4) {
            float4 h4[8];
            #pragma unroll
            for (int i = 0; i < 8; i++)
                h4[i] = Hsm4[(r0 + i) * 32 + (kk >> 2)];

            #pragma unroll
            for (int j = 0; j < 4; j++) {
                const ulonglong2 wA = *reinterpret_cast<const ulonglong2*>(
                    &Wsm[(kk + j) * OUT_F + n0]);
                const ulonglong2 wB = *reinterpret_cast<const ulonglong2*>(
                    &Wsm[(kk + j) * OUT_F + n0 + 4]);
                #pragma unroll
                for (int i = 0; i < 8; i++) {
                    const float a = (j == 0) ? h4[i].x : (j == 1) ? h4[i].y
                                  : (j == 2) ? h4[i].z : h4[i].w;
                    unsigned long long aa;
                    asm("mov.b64 %0, {%1, %1};" : "=l"(aa) : "f"(a));
                    asm("fma.rn.f32x2 %0, %1, %2, %0;" : "+l"(acc[i][0]) : "l"(aa), "l"(wA.x));
                    asm("fma.rn.f32x2 %0, %1, %2, %0;" : "+l"(acc[i][1]) : "l"(aa), "l"(wA.y));
                    asm("fma.rn.f32x2 %0, %1, %2, %0;" : "+l"(acc[i][2]) : "l"(aa), "l"(wB.x));
                    asm("fma.rn.f32x2 %0, %1, %2, %0;" : "+l"(acc[i][3]) : "l"(aa), "l"(wB.y));
                }
            }
        }

        const int m0 = tile * TILE_M;
        #pragma unroll
        for (int i = 0; i < 8; i++) {
            const int m = m0 + r0 + i;
            if (m < N_NODES) {
                float lo, hi;
                float o[8];
                #pragma unroll
                for (int j = 0; j < 4; j++) {
                    asm("mov.b64 {%0, %1}, %2;" : "=f"(lo), "=f"(hi) : "l"(acc[i][j]));
                    o[2 * j]     = lo + bb[2 * j];
                    o[2 * j + 1] = hi + bb[2 * j + 1];
                }
                float4* orow = reinterpret_cast<float4*>(out + (size_t)m * OUT_F + n0);
                orow[0] = make_float4(o[0], o[1], o[2], o[3]);
                orow[1] = make_float4(o[4], o[5], o[6], o[7]);
            }
        }
        __syncthreads();
    }
}

// ---------------------------------------------------------------------------
extern "C" void kernel_launch(void* const* d_in, const int* in_sizes, int n_in,
                              void* d_out, int out_size) {
    const float* x  = nullptr;
    const int*   ei = nullptr;
    const float* W  = nullptr;
    const float* b  = nullptr;

    for (int i = 0; i < n_in; i++) {
        switch (in_sizes[i]) {
            case N_NODES * IN_F:  x  = (const float*)d_in[i]; break;
            case 2 * N_EDGES:     ei = (const int*)d_in[i];   break;
            case OUT_F * IN_F:    W  = (const float*)d_in[i]; break;
            case OUT_F:           b  = (const float*)d_in[i]; break;
            default: break;
        }
    }

    float* out = (float*)d_out;

    void* cnt4_ptr = nullptr;
    cudaGetSymbolAddress(&cnt4_ptr, g_cnt4);
    cudaMemsetAsync(cnt4_ptr, 0, 4 * N_NODES * sizeof(int));

    hist_kernel<<<HIST_BLOCKS, 256>>>(ei, reinterpret_cast<const float4*>(x));
    scan_fused_kernel<<<SCAN_B, SCAN_T>>>();
    fill_kernel<<<(N_EDGES / 4 + 255) / 256, 256>>>(ei);

    const int agg_blocks = (N_NODES * 32 + 255) / 256;   // 6250
    agg_kernel<<<agg_blocks, 256>>>();

    const int smem_bytes = 3 * IN_F * OUT_F * (int)sizeof(float);  // 192KB
    cudaFuncSetAttribute(gemm_kernel, cudaFuncAttributeMaxDynamicSharedMemorySize,
                         smem_bytes);
    gemm_kernel<<<NUM_SM, 256, smem_bytes>>>(out, W, b);
}

// round 14
// speedup vs baseline: 1.2178x; 1.1492x over previous
#include <cuda_runtime.h>
#include <cuda_fp16.h>
#include <stdint.h>

#define N_NODES  50000
#define N_EDGES  800000
#define IN_F     128
#define OUT_F    128

#define SCAN_T   256
#define SCAN_B   ((N_NODES + SCAN_T - 1) / SCAN_T)   // 196

#define TILE_M   128
#define N_TILES  ((N_NODES + TILE_M - 1) / TILE_M)   // 391

// -------------------- device scratch (no allocation allowed) ---------------
__device__ __align__(16) __half g_xh[N_NODES * IN_F];    // fp16 copy of x
__device__ __align__(16) __half g_aggh[N_NODES * IN_F];  // fp16 normalized h
__device__ __align__(16) __half g_wh[OUT_F * IN_F];      // fp16 copy of W
__device__ int   g_cnt4[4 * N_NODES];   // replicated histograms (stripe = edge%4)
__device__ int   g_base4[4 * N_NODES];  // per-(node,replica) bases; row0 = CSR start
__device__ int   g_cnt[N_NODES];        // per-node totals
__device__ __align__(16) int g_rank[N_EDGES];  // rank within (node,replica)
__device__ int   g_srcs[N_EDGES];       // edge sources grouped by dst
__device__ int   g_bsums[SCAN_B];
__device__ int   g_scan_done;           // grid-barrier counter (reset by hist)

// -------------------- 0) convert x->fp16 and W->fp16 (wide streaming) ------
__global__ void __launch_bounds__(256)
convert_kernel(const float4* __restrict__ x4, const float* __restrict__ W) {
    const int gtid   = blockIdx.x * blockDim.x + threadIdx.x;
    const int stride = gridDim.x * blockDim.x;
    uint2* xh2 = reinterpret_cast<uint2*>(g_xh);
    const int n4 = N_NODES * IN_F / 4;   // 1.6M
    for (int i = gtid; i < n4; i += stride) {
        float4 v = x4[i];
        __half2 h0 = __floats2half2_rn(v.x, v.y);
        __half2 h1 = __floats2half2_rn(v.z, v.w);
        uint2 p;
        p.x = *reinterpret_cast<unsigned*>(&h0);
        p.y = *reinterpret_cast<unsigned*>(&h1);
        xh2[i] = p;
    }
    // W: 16384 floats -> 8192 half2
    unsigned* wh2 = reinterpret_cast<unsigned*>(g_wh);
    if (gtid < OUT_F * IN_F / 2) {
        float2 w = reinterpret_cast<const float2*>(W)[gtid];
        __half2 h = __floats2half2_rn(w.x, w.y);
        wh2[gtid] = *reinterpret_cast<unsigned*>(&h);
    }
}

// -------------------- 1) histogram (replicated) + rank capture -------------
__global__ void __launch_bounds__(256)
hist_kernel(const int* __restrict__ ei) {
    const int gtid = blockIdx.x * blockDim.x + threadIdx.x;
    if (gtid == 0) g_scan_done = 0;   // reset grid barrier for scan kernel
    const int e4 = gtid;
    if (e4 >= N_EDGES / 4) return;
    int4 d = reinterpret_cast<const int4*>(ei + N_EDGES)[e4];
    d.x = min(max(d.x, 0), N_NODES - 1);
    d.y = min(max(d.y, 0), N_NODES - 1);
    d.z = min(max(d.z, 0), N_NODES - 1);
    d.w = min(max(d.w, 0), N_NODES - 1);
    int4 r;
    r.x = atomicAdd(&g_cnt4[0 * N_NODES + d.x], 1);
    r.y = atomicAdd(&g_cnt4[1 * N_NODES + d.y], 1);
    r.z = atomicAdd(&g_cnt4[2 * N_NODES + d.z], 1);
    r.w = atomicAdd(&g_cnt4[3 * N_NODES + d.w], 1);
    reinterpret_cast<int4*>(g_rank)[e4] = r;
}

// -------------------- 2) fused exclusive scan (single kernel) --------------
__global__ void __launch_bounds__(SCAN_T)
scan_fused_kernel() {
    __shared__ int st[SCAN_T];
    __shared__ int sb[SCAN_T];
    const int tid = threadIdx.x;
    const int gid = blockIdx.x * SCAN_T + tid;

    int c0 = 0, c1 = 0, c2 = 0, tot = 0;
    if (gid < N_NODES) {
        c0 = g_cnt4[gid];
        c1 = g_cnt4[N_NODES + gid];
        c2 = g_cnt4[2 * N_NODES + gid];
        tot = c0 + c1 + c2 + g_cnt4[3 * N_NODES + gid];
        g_cnt[gid] = tot;
    }
    st[tid] = tot;
    __syncthreads();
    #pragma unroll
    for (int o = 1; o < SCAN_T; o <<= 1) {
        int t = (tid >= o) ? st[tid - o] : 0;
        __syncthreads();
        st[tid] += t;
        __syncthreads();
    }

    if (tid == 0) {
        g_bsums[blockIdx.x] = st[SCAN_T - 1];
        __threadfence();
        atomicAdd(&g_scan_done, 1);
    }
    if (tid == 0) {
        int v;
        do {
            asm volatile("ld.global.acquire.gpu.b32 %0, [%1];"
                         : "=r"(v) : "l"(&g_scan_done));
        } while (v < (int)gridDim.x);
    }
    __syncthreads();

    int bv = (tid < SCAN_B) ? *(volatile int*)&g_bsums[tid] : 0;
    sb[tid] = bv;
    __syncthreads();
    #pragma unroll
    for (int o = 1; o < SCAN_T; o <<= 1) {
        int t = (tid >= o) ? sb[tid - o] : 0;
        __syncthreads();
        sb[tid] += t;
        __syncthreads();
    }
    const int base = (blockIdx.x > 0) ? sb[blockIdx.x - 1] : 0;

    if (gid < N_NODES) {
        const int excl = base + st[tid] - tot;
        g_base4[gid]               = excl;       // row0 base == CSR row start
        g_base4[N_NODES + gid]     = excl + c0;
        g_base4[2 * N_NODES + gid] = excl + c0 + c1;
        g_base4[3 * N_NODES + gid] = excl + c0 + c1 + c2;
    }
}

// -------------------- 3) bucket-fill: NO atomics (base + rank) -------------
__global__ void fill_kernel(const int* __restrict__ ei) {
    const int e4 = blockIdx.x * blockDim.x + threadIdx.x;
    if (e4 >= N_EDGES / 4) return;
    int4 s = reinterpret_cast<const int4*>(ei)[e4];
    int4 d = reinterpret_cast<const int4*>(ei + N_EDGES)[e4];
    int4 r = reinterpret_cast<const int4*>(g_rank)[e4];
    s.x = min(max(s.x, 0), N_NODES - 1);
    s.y = min(max(s.y, 0), N_NODES - 1);
    s.z = min(max(s.z, 0), N_NODES - 1);
    s.w = min(max(s.w, 0), N_NODES - 1);
    d.x = min(max(d.x, 0), N_NODES - 1);
    d.y = min(max(d.y, 0), N_NODES - 1);
    d.z = min(max(d.z, 0), N_NODES - 1);
    d.w = min(max(d.w, 0), N_NODES - 1);
    const int p0 = g_base4[0 * N_NODES + d.x] + r.x;
    const int p1 = g_base4[1 * N_NODES + d.y] + r.y;
    const int p2 = g_base4[2 * N_NODES + d.z] + r.z;
    const int p3 = g_base4[3 * N_NODES + d.w] + r.w;
    g_srcs[p0] = s.x;
    g_srcs[p1] = s.y;
    g_srcs[p2] = s.z;
    g_srcs[p3] = s.w;
}

// -------------------- 4) gather-aggregate: fp16 in, fp16 out ---------------
__device__ __forceinline__ void acc_h2(float4& a, uint2 p) {
    __half2 h0 = *reinterpret_cast<__half2*>(&p.x);
    __half2 h1 = *reinterpret_cast<__half2*>(&p.y);
    float2 f0 = __half22float2(h0);
    float2 f1 = __half22float2(h1);
    a.x += f0.x; a.y += f0.y; a.z += f1.x; a.w += f1.y;
}

__global__ void __launch_bounds__(256, 6)
agg_kernel() {
    const int node = (blockIdx.x * blockDim.x + threadIdx.x) >> 5;
    if (node >= N_NODES) return;
    const int lane = threadIdx.x & 31;

    const int start = g_base4[node];   // row0 base == CSR row start
    const int cnt   = g_cnt[node];
    const int end   = start + cnt;

    const uint2* xh2 = reinterpret_cast<const uint2*>(g_xh);

    float4 a0 = make_float4(0.f, 0.f, 0.f, 0.f);
    float4 a1 = make_float4(0.f, 0.f, 0.f, 0.f);

    int e = start;
    for (; e + 7 < end; e += 8) {
        int s0 = g_srcs[e],     s1 = g_srcs[e + 1];
        int s2 = g_srcs[e + 2], s3 = g_srcs[e + 3];
        int s4 = g_srcs[e + 4], s5 = g_srcs[e + 5];
        int s6 = g_srcs[e + 6], s7 = g_srcs[e + 7];
        uint2 p0 = __ldg(&xh2[s0 * 32 + lane]);
        uint2 p1 = __ldg(&xh2[s1 * 32 + lane]);
        uint2 p2 = __ldg(&xh2[s2 * 32 + lane]);
        uint2 p3 = __ldg(&xh2[s3 * 32 + lane]);
        uint2 p4 = __ldg(&xh2[s4 * 32 + lane]);
        uint2 p5 = __ldg(&xh2[s5 * 32 + lane]);
        uint2 p6 = __ldg(&xh2[s6 * 32 + lane]);
        uint2 p7 = __ldg(&xh2[s7 * 32 + lane]);
        acc_h2(a0, p0); acc_h2(a1, p1); acc_h2(a0, p2); acc_h2(a1, p3);
        acc_h2(a0, p4); acc_h2(a1, p5); acc_h2(a0, p6); acc_h2(a1, p7);
    }
    const int rem = end - e;
    if (rem > 0) {
        int idx[7];
        #pragma unroll
        for (int i = 0; i < 7; i++)
            idx[i] = (i < rem) ? g_srcs[e + i] : 0;
        uint2 v[7];
        #pragma unroll
        for (int i = 0; i < 7; i++)
            if (i < rem) v[i] = __ldg(&xh2[idx[i] * 32 + lane]);
        #pragma unroll
        for (int i = 0; i < 7; i++)
            if (i < rem) {
                if (i & 1) acc_h2(a1, v[i]); else acc_h2(a0, v[i]);
            }
    }

    const float inv = 1.0f / fmaxf((float)cnt, 1.0f);
    __half2 h0 = __floats2half2_rn((a0.x + a1.x) * inv, (a0.y + a1.y) * inv);
    __half2 h1 = __floats2half2_rn((a0.z + a1.z) * inv, (a0.w + a1.w) * inv);
    uint2 p;
    p.x = *reinterpret_cast<unsigned*>(&h0);
    p.y = *reinterpret_cast<unsigned*>(&h1);
    reinterpret_cast<uint2*>(g_aggh)[(size_t)node * 32 + lane] = p;
}

// -------------------- 5) tensor-core GEMM: out = h @ W^T + b ---------------
// HMMA m16n8k16, fp16 inputs, fp32 accumulate. Block = 8 warps; warp w owns
// rows [m0 + 16w, +16), all 128 cols. Fragments loaded directly from global
// (A rows and W rows are contiguous-k 32-bit pairs; all L1/L2-resident).
__global__ void __launch_bounds__(256)
gemm_kernel(float* __restrict__ out, const float* __restrict__ b) {
    const int warp = threadIdx.x >> 5;
    const int lane = threadIdx.x & 31;
    const int q    = lane & 3;        // thread-in-group
    const int g    = lane >> 2;       // group id 0..7
    const int m0   = blockIdx.x * TILE_M + warp * 16;

    // A rows this thread touches (clamped; stores are guarded)
    const int rowLo = min(m0 + g,     N_NODES - 1);
    const int rowHi = min(m0 + g + 8, N_NODES - 1);
    const __half* A = g_aggh;
    const __half* Bw = g_wh;

    float acc[16][4];
    #pragma unroll
    for (int t = 0; t < 16; t++)
        #pragma unroll
        for (int j = 0; j < 4; j++) acc[t][j] = 0.0f;

    #pragma unroll
    for (int ks = 0; ks < 8; ks++) {
        const int k0 = ks * 16;
        const int ka = k0 + 2 * q;
        unsigned a0 = *reinterpret_cast<const unsigned*>(&A[(size_t)rowLo * IN_F + ka]);
        unsigned a1 = *reinterpret_cast<const unsigned*>(&A[(size_t)rowHi * IN_F + ka]);
        unsigned a2 = *reinterpret_cast<const unsigned*>(&A[(size_t)rowLo * IN_F + ka + 8]);
        unsigned a3 = *reinterpret_cast<const unsigned*>(&A[(size_t)rowHi * IN_F + ka + 8]);

        #pragma unroll
        for (int t = 0; t < 16; t++) {
            const int n = t * 8 + g;   // B col = W row
            unsigned b0 = *reinterpret_cast<const unsigned*>(&Bw[n * IN_F + ka]);
            unsigned b1 = *reinterpret_cast<const unsigned*>(&Bw[n * IN_F + ka + 8]);
            asm volatile(
                "mma.sync.aligned.m16n8k16.row.col.f32.f16.f16.f32 "
                "{%0,%1,%2,%3}, {%4,%5,%6,%7}, {%8,%9}, {%0,%1,%2,%3};"
                : "+f"(acc[t][0]), "+f"(acc[t][1]), "+f"(acc[t][2]), "+f"(acc[t][3])
                : "r"(a0), "r"(a1), "r"(a2), "r"(a3), "r"(b0), "r"(b1));
        }
    }

    // Store: c0,c1 -> (row = m0+g, col = n0+2q,2q+1); c2,c3 -> row+8
    const int mLo = m0 + g;
    const int mHi = m0 + g + 8;
    #pragma unroll
    for (int t = 0; t < 16; t++) {
        const int col = t * 8 + 2 * q;
        const float b0v = b[col];
        const float b1v = b[col + 1];
        if (mLo < N_NODES) {
            float2 o = make_float2(acc[t][0] + b0v, acc[t][1] + b1v);
            *reinterpret_cast<float2*>(out + (size_t)mLo * OUT_F + col) = o;
        }
        if (mHi < N_NODES) {
            float2 o = make_float2(acc[t][2] + b0v, acc[t][3] + b1v);
            *reinterpret_cast<float2*>(out + (size_t)mHi * OUT_F + col) = o;
        }
    }
}

// ---------------------------------------------------------------------------
extern "C" void kernel_launch(void* const* d_in, const int* in_sizes, int n_in,
                              void* d_out, int out_size) {
    const float* x  = nullptr;
    const int*   ei = nullptr;
    const float* W  = nullptr;
    const float* b  = nullptr;

    for (int i = 0; i < n_in; i++) {
        switch (in_sizes[i]) {
            case N_NODES * IN_F:  x  = (const float*)d_in[i]; break;
            case 2 * N_EDGES:     ei = (const int*)d_in[i];   break;
            case OUT_F * IN_F:    W  = (const float*)d_in[i]; break;
            case OUT_F:           b  = (const float*)d_in[i]; break;
            default: break;
        }
    }

    float* out = (float*)d_out;

    void* cnt4_ptr = nullptr;
    cudaGetSymbolAddress(&cnt4_ptr, g_cnt4);
    cudaMemsetAsync(cnt4_ptr, 0, 4 * N_NODES * sizeof(int));

    convert_kernel<<<2048, 256>>>(reinterpret_cast<const float4*>(x), W);
    hist_kernel<<<(N_EDGES / 4 + 255) / 256, 256>>>(ei);
    scan_fused_kernel<<<SCAN_B, SCAN_T>>>();
    fill_kernel<<<(N_EDGES / 4 + 255) / 256, 256>>>(ei);

    const int agg_blocks = (N_NODES * 32 + 255) / 256;   // 6250
    agg_kernel<<<agg_blocks, 256>>>();

    gemm_kernel<<<N_TILES, 256>>>(out, b);
}

// round 15
// speedup vs baseline: 1.5135x; 1.2428x over previous
#include <cuda_runtime.h>
#include <cuda_fp16.h>
#include <stdint.h>

#define N_NODES  50000
#define N_EDGES  800000
#define IN_F     128
#define OUT_F    128

#define SCAN_T   256
#define SCAN_B   ((N_NODES + SCAN_T - 1) / SCAN_T)   // 196

#define NUM_SM   148
#define TILE_M   128
#define N_TILES  ((N_NODES + TILE_M - 1) / TILE_M)   // 391

#define W_PAD    136   // W smem row stride in halves (128 + 8 -> bank-conflict-free)

// -------------------- device scratch (no allocation allowed) ---------------
__device__ __align__(16) __half g_xh[N_NODES * IN_F];    // fp16 copy of x
__device__ __align__(16) __half g_aggh[N_NODES * IN_F];  // fp16 normalized h
__device__ __align__(16) __half g_wh[OUT_F * IN_F];      // fp16 copy of W
__device__ int   g_cnt4[4 * N_NODES];   // replicated histograms (stripe = edge%4)
__device__ int   g_base4[4 * N_NODES];  // per-(node,replica) bases; row0 = CSR start
__device__ int   g_cnt[N_NODES];        // per-node totals
__device__ __align__(16) int g_rank[N_EDGES];  // rank within (node,replica)
__device__ int   g_srcs[N_EDGES];       // edge sources grouped by dst
__device__ int   g_bsums[SCAN_B];
__device__ int   g_scan_done;           // grid-barrier counter (reset by hist)

// -------------------- 0) convert x,W -> fp16 AND zero g_cnt4 ---------------
__global__ void __launch_bounds__(256)
convert_kernel(const float4* __restrict__ x4, const float* __restrict__ W) {
    const int gtid   = blockIdx.x * blockDim.x + threadIdx.x;
    const int stride = gridDim.x * blockDim.x;
    uint2* xh2 = reinterpret_cast<uint2*>(g_xh);
    const int n4 = N_NODES * IN_F / 4;   // 1.6M
    for (int i = gtid; i < n4; i += stride) {
        float4 v = x4[i];
        __half2 h0 = __floats2half2_rn(v.x, v.y);
        __half2 h1 = __floats2half2_rn(v.z, v.w);
        uint2 p;
        p.x = *reinterpret_cast<unsigned*>(&h0);
        p.y = *reinterpret_cast<unsigned*>(&h1);
        xh2[i] = p;
    }
    // zero histogram replicas (replaces cudaMemsetAsync)
    int4* cnt4v = reinterpret_cast<int4*>(g_cnt4);
    for (int i = gtid; i < N_NODES; i += stride)   // 4*N_NODES ints = N_NODES int4
        cnt4v[i] = make_int4(0, 0, 0, 0);
    // W: 16384 floats -> 8192 half2
    unsigned* wh2 = reinterpret_cast<unsigned*>(g_wh);
    if (gtid < OUT_F * IN_F / 2) {
        float2 w = reinterpret_cast<const float2*>(W)[gtid];
        __half2 h = __floats2half2_rn(w.x, w.y);
        wh2[gtid] = *reinterpret_cast<unsigned*>(&h);
    }
}

// -------------------- 1) histogram (replicated) + rank capture -------------
__global__ void __launch_bounds__(256)
hist_kernel(const int* __restrict__ ei) {
    const int gtid = blockIdx.x * blockDim.x + threadIdx.x;
    if (gtid == 0) g_scan_done = 0;   // reset grid barrier for scan kernel
    const int e4 = gtid;
    if (e4 >= N_EDGES / 4) return;
    int4 d = reinterpret_cast<const int4*>(ei + N_EDGES)[e4];
    d.x = min(max(d.x, 0), N_NODES - 1);
    d.y = min(max(d.y, 0), N_NODES - 1);
    d.z = min(max(d.z, 0), N_NODES - 1);
    d.w = min(max(d.w, 0), N_NODES - 1);
    int4 r;
    r.x = atomicAdd(&g_cnt4[0 * N_NODES + d.x], 1);
    r.y = atomicAdd(&g_cnt4[1 * N_NODES + d.y], 1);
    r.z = atomicAdd(&g_cnt4[2 * N_NODES + d.z], 1);
    r.w = atomicAdd(&g_cnt4[3 * N_NODES + d.w], 1);
    reinterpret_cast<int4*>(g_rank)[e4] = r;
}

// -------------------- 2) fused exclusive scan (single kernel) --------------
__global__ void __launch_bounds__(SCAN_T)
scan_fused_kernel() {
    __shared__ int st[SCAN_T];
    __shared__ int sb[SCAN_T];
    const int tid = threadIdx.x;
    const int gid = blockIdx.x * SCAN_T + tid;

    int c0 = 0, c1 = 0, c2 = 0, tot = 0;
    if (gid < N_NODES) {
        c0 = g_cnt4[gid];
        c1 = g_cnt4[N_NODES + gid];
        c2 = g_cnt4[2 * N_NODES + gid];
        tot = c0 + c1 + c2 + g_cnt4[3 * N_NODES + gid];
        g_cnt[gid] = tot;
    }
    st[tid] = tot;
    __syncthreads();
    #pragma unroll
    for (int o = 1; o < SCAN_T; o <<= 1) {
        int t = (tid >= o) ? st[tid - o] : 0;
        __syncthreads();
        st[tid] += t;
        __syncthreads();
    }

    if (tid == 0) {
        g_bsums[blockIdx.x] = st[SCAN_T - 1];
        __threadfence();
        atomicAdd(&g_scan_done, 1);
    }
    if (tid == 0) {
        int v;
        do {
            asm volatile("ld.global.acquire.gpu.b32 %0, [%1];"
                         : "=r"(v) : "l"(&g_scan_done));
        } while (v < (int)gridDim.x);
    }
    __syncthreads();

    int bv = (tid < SCAN_B) ? *(volatile int*)&g_bsums[tid] : 0;
    sb[tid] = bv;
    __syncthreads();
    #pragma unroll
    for (int o = 1; o < SCAN_T; o <<= 1) {
        int t = (tid >= o) ? sb[tid - o] : 0;
        __syncthreads();
        sb[tid] += t;
        __syncthreads();
    }
    const int base = (blockIdx.x > 0) ? sb[blockIdx.x - 1] : 0;

    if (gid < N_NODES) {
        const int excl = base + st[tid] - tot;
        g_base4[gid]               = excl;       // row0 base == CSR row start
        g_base4[N_NODES + gid]     = excl + c0;
        g_base4[2 * N_NODES + gid] = excl + c0 + c1;
        g_base4[3 * N_NODES + gid] = excl + c0 + c1 + c2;
    }
}

// -------------------- 3) bucket-fill: NO atomics (base + rank) -------------
__global__ void fill_kernel(const int* __restrict__ ei) {
    const int e4 = blockIdx.x * blockDim.x + threadIdx.x;
    if (e4 >= N_EDGES / 4) return;
    int4 s = reinterpret_cast<const int4*>(ei)[e4];
    int4 d = reinterpret_cast<const int4*>(ei + N_EDGES)[e4];
    int4 r = reinterpret_cast<const int4*>(g_rank)[e4];
    s.x = min(max(s.x, 0), N_NODES - 1);
    s.y = min(max(s.y, 0), N_NODES - 1);
    s.z = min(max(s.z, 0), N_NODES - 1);
    s.w = min(max(s.w, 0), N_NODES - 1);
    d.x = min(max(d.x, 0), N_NODES - 1);
    d.y = min(max(d.y, 0), N_NODES - 1);
    d.z = min(max(d.z, 0), N_NODES - 1);
    d.w = min(max(d.w, 0), N_NODES - 1);
    const int p0 = g_base4[0 * N_NODES + d.x] + r.x;
    const int p1 = g_base4[1 * N_NODES + d.y] + r.y;
    const int p2 = g_base4[2 * N_NODES + d.z] + r.z;
    const int p3 = g_base4[3 * N_NODES + d.w] + r.w;
    g_srcs[p0] = s.x;
    g_srcs[p1] = s.y;
    g_srcs[p2] = s.z;
    g_srcs[p3] = s.w;
}

// -------------------- 4) gather-aggregate: fp16 in, fp16 out ---------------
__device__ __forceinline__ void acc_h2(float4& a, uint2 p) {
    __half2 h0 = *reinterpret_cast<__half2*>(&p.x);
    __half2 h1 = *reinterpret_cast<__half2*>(&p.y);
    float2 f0 = __half22float2(h0);
    float2 f1 = __half22float2(h1);
    a.x += f0.x; a.y += f0.y; a.z += f1.x; a.w += f1.y;
}

__global__ void __launch_bounds__(256, 6)
agg_kernel() {
    const int node = (blockIdx.x * blockDim.x + threadIdx.x) >> 5;
    if (node >= N_NODES) return;
    const int lane = threadIdx.x & 31;

    const int start = g_base4[node];   // row0 base == CSR row start
    const int cnt   = g_cnt[node];
    const int end   = start + cnt;

    const uint2* xh2 = reinterpret_cast<const uint2*>(g_xh);

    float4 a0 = make_float4(0.f, 0.f, 0.f, 0.f);
    float4 a1 = make_float4(0.f, 0.f, 0.f, 0.f);

    int e = start;
    for (; e + 7 < end; e += 8) {
        int s0 = g_srcs[e],     s1 = g_srcs[e + 1];
        int s2 = g_srcs[e + 2], s3 = g_srcs[e + 3];
        int s4 = g_srcs[e + 4], s5 = g_srcs[e + 5];
        int s6 = g_srcs[e + 6], s7 = g_srcs[e + 7];
        uint2 p0 = __ldg(&xh2[s0 * 32 + lane]);
        uint2 p1 = __ldg(&xh2[s1 * 32 + lane]);
        uint2 p2 = __ldg(&xh2[s2 * 32 + lane]);
        uint2 p3 = __ldg(&xh2[s3 * 32 + lane]);
        uint2 p4 = __ldg(&xh2[s4 * 32 + lane]);
        uint2 p5 = __ldg(&xh2[s5 * 32 + lane]);
        uint2 p6 = __ldg(&xh2[s6 * 32 + lane]);
        uint2 p7 = __ldg(&xh2[s7 * 32 + lane]);
        acc_h2(a0, p0); acc_h2(a1, p1); acc_h2(a0, p2); acc_h2(a1, p3);
        acc_h2(a0, p4); acc_h2(a1, p5); acc_h2(a0, p6); acc_h2(a1, p7);
    }
    const int rem = end - e;
    if (rem > 0) {
        int idx[7];
        #pragma unroll
        for (int i = 0; i < 7; i++)
            idx[i] = (i < rem) ? g_srcs[e + i] : 0;
        uint2 v[7];
        #pragma unroll
        for (int i = 0; i < 7; i++)
            if (i < rem) v[i] = __ldg(&xh2[idx[i] * 32 + lane]);
        #pragma unroll
        for (int i = 0; i < 7; i++)
            if (i < rem) {
                if (i & 1) acc_h2(a1, v[i]); else acc_h2(a0, v[i]);
            }
    }

    const float inv = 1.0f / fmaxf((float)cnt, 1.0f);
    __half2 h0 = __floats2half2_rn((a0.x + a1.x) * inv, (a0.y + a1.y) * inv);
    __half2 h1 = __floats2half2_rn((a0.z + a1.z) * inv, (a0.w + a1.w) * inv);
    uint2 p;
    p.x = *reinterpret_cast<unsigned*>(&h0);
    p.y = *reinterpret_cast<unsigned*>(&h1);
    reinterpret_cast<uint2*>(g_aggh)[(size_t)node * 32 + lane] = p;
}

// -------------------- 5) tensor-core GEMM (persistent, W in smem) ----------
// HMMA m16n8k16 fp16->fp32. 148 persistent blocks; W staged into smem ONCE
// per block (padded rows: stride W_PAD halves -> B-frag LDS is conflict-free).
// A fragments from global (L2-resident).
__global__ void __launch_bounds__(256)
gemm_kernel(float* __restrict__ out, const float* __restrict__ b) {
    __shared__ __half Wsm[OUT_F * W_PAD];   // 128*136*2 = 34816 B

    const int tid  = threadIdx.x;
    const int warp = tid >> 5;
    const int lane = tid & 31;
    const int q    = lane & 3;
    const int g    = lane >> 2;

    // stage W: Wsm[n][k] = g_wh[n*128 + k], row stride W_PAD
    for (int i = tid; i < OUT_F * (IN_F / 4); i += 256) {
        const int n = i >> 5;           // 32 uint2 per row
        const int c = i & 31;           // uint2 index within row
        uint2 v = reinterpret_cast<const uint2*>(g_wh)[n * 32 + c];
        *reinterpret_cast<uint2*>(&Wsm[n * W_PAD + c * 4]) = v;
    }
    __syncthreads();

    const __half* A = g_aggh;

    for (int tile = blockIdx.x; tile < N_TILES; tile += NUM_SM) {
        const int m0 = tile * TILE_M + warp * 16;
        const int rowLo = min(m0 + g,     N_NODES - 1);
        const int rowHi = min(m0 + g + 8, N_NODES - 1);

        float acc[16][4];
        #pragma unroll
        for (int t = 0; t < 16; t++)
            #pragma unroll
            for (int j = 0; j < 4; j++) acc[t][j] = 0.0f;

        #pragma unroll
        for (int ks = 0; ks < 8; ks++) {
            const int ka = ks * 16 + 2 * q;
            unsigned a0 = *reinterpret_cast<const unsigned*>(&A[(size_t)rowLo * IN_F + ka]);
            unsigned a1 = *reinterpret_cast<const unsigned*>(&A[(size_t)rowHi * IN_F + ka]);
            unsigned a2 = *reinterpret_cast<const unsigned*>(&A[(size_t)rowLo * IN_F + ka + 8]);
            unsigned a3 = *reinterpret_cast<const unsigned*>(&A[(size_t)rowHi * IN_F + ka + 8]);

            #pragma unroll
            for (int t = 0; t < 16; t++) {
                const int n = t * 8 + g;
                unsigned b0 = *reinterpret_cast<const unsigned*>(&Wsm[n * W_PAD + ka]);
                unsigned b1 = *reinterpret_cast<const unsigned*>(&Wsm[n * W_PAD + ka + 8]);
                asm volatile(
                    "mma.sync.aligned.m16n8k16.row.col.f32.f16.f16.f32 "
                    "{%0,%1,%2,%3}, {%4,%5,%6,%7}, {%8,%9}, {%0,%1,%2,%3};"
                    : "+f"(acc[t][0]), "+f"(acc[t][1]), "+f"(acc[t][2]), "+f"(acc[t][3])
                    : "r"(a0), "r"(a1), "r"(a2), "r"(a3), "r"(b0), "r"(b1));
            }
        }

        const int mLo = m0 + g;
        const int mHi = m0 + g + 8;
        #pragma unroll
        for (int t = 0; t < 16; t++) {
            const int col = t * 8 + 2 * q;
            const float b0v = b[col];
            const float b1v = b[col + 1];
            if (mLo < N_NODES) {
                float2 o = make_float2(acc[t][0] + b0v, acc[t][1] + b1v);
                *reinterpret_cast<float2*>(out + (size_t)mLo * OUT_F + col) = o;
            }
            if (mHi < N_NODES) {
                float2 o = make_float2(acc[t][2] + b0v, acc[t][3] + b1v);
                *reinterpret_cast<float2*>(out + (size_t)mHi * OUT_F + col) = o;
            }
        }
    }
}

// ---------------------------------------------------------------------------
extern "C" void kernel_launch(void* const* d_in, const int* in_sizes, int n_in,
                              void* d_out, int out_size) {
    const float* x  = nullptr;
    const int*   ei = nullptr;
    const float* W  = nullptr;
    const float* b  = nullptr;

    for (int i = 0; i < n_in; i++) {
        switch (in_sizes[i]) {
            case N_NODES * IN_F:  x  = (const float*)d_in[i]; break;
            case 2 * N_EDGES:     ei = (const int*)d_in[i];   break;
            case OUT_F * IN_F:    W  = (const float*)d_in[i]; break;
            case OUT_F:           b  = (const float*)d_in[i]; break;
            default: break;
        }
    }

    float* out = (float*)d_out;

    convert_kernel<<<2048, 256>>>(reinterpret_cast<const float4*>(x), W);
    hist_kernel<<<(N_EDGES / 4 + 255) / 256, 256>>>(ei);
    scan_fused_kernel<<<SCAN_B, SCAN_T>>>();
    fill_kernel<<<(N_EDGES / 4 + 255) / 256, 256>>>(ei);

    const int agg_blocks = (N_NODES * 32 + 255) / 256;   // 6250
    agg_kernel<<<agg_blocks, 256>>>();

    gemm_kernel<<<NUM_SM, 256>>>(out, b);
}